// round 5
// baseline (speedup 1.0000x reference)
#include <cuda_runtime.h>
#include <math.h>
#include <stdint.h>

// ---------------- problem constants ----------------
#define B_   2
#define S_   2048
#define H_   1024
#define NH_  16
#define HD_  64
#define T_   (B_*S_)      // 4096 tokens
#define FFN_ 4096
#define ROT_ 16

// ---------------- static scratch ----------------
__device__ float d_xn [T_*H_];
__device__ float d_big[T_*FFN_];
__device__ float d_q  [T_*H_];
__device__ float d_k  [T_*H_];
__device__ float d_v  [T_*H_];
__device__ float d_o  [T_*H_];
__device__ float d_x1 [T_*H_];
// preprocessed weights (rounded to tf32, k-pair-interleaved; vals also transposed)
__device__ float d_qvT[H_*H_];
__device__ float d_kvT[H_*H_];
__device__ float d_vvT[H_*H_];
__device__ float d_pvT[H_*H_];
__device__ float d_fvT[H_*FFN_];
__device__ float d_qkR[H_*H_];
__device__ float d_kkR[H_*H_];
__device__ float d_vkR[H_*H_];
__device__ float d_pkR[H_*H_];
__device__ float d_fkR[FFN_*H_];

// ---------------- helpers ----------------
__device__ __forceinline__ float gelu_exact(float x) {
    return 0.5f * x * (1.0f + erff(x * 0.7071067811865475f));
}
__device__ __forceinline__ uint32_t f2tf(float f) {
    uint32_t u;
    asm("cvt.rna.tf32.f32 %0, %1;" : "=r"(u) : "f"(f));
    return u;
}
__device__ __forceinline__ float rnd_tf(float f) { return __uint_as_float(f2tf(f)); }

// k-permutation within groups of 8: pos(k) = 2*(k&3) + ((k>>2)&1)
__device__ __forceinline__ int pos8(int k) { return 2 * (k & 3) + ((k >> 2) & 1); }

__device__ __forceinline__ void mma_tf32(float* d, const uint32_t* a, const uint32_t* b) {
    asm volatile(
        "mma.sync.aligned.m16n8k8.row.col.f32.tf32.tf32.f32 "
        "{%0,%1,%2,%3}, {%4,%5,%6,%7}, {%8,%9}, {%0,%1,%2,%3};\n"
        : "+f"(d[0]), "+f"(d[1]), "+f"(d[2]), "+f"(d[3])
        : "r"(a[0]), "r"(a[1]), "r"(a[2]), "r"(a[3]), "r"(b[0]), "r"(b[1]));
}
__device__ __forceinline__ void cp_async16(uint32_t smem_addr, const void* gptr) {
    asm volatile("cp.async.cg.shared.global [%0], [%1], 16;\n" :: "r"(smem_addr), "l"(gptr));
}
#define CP_COMMIT() asm volatile("cp.async.commit_group;\n" ::: "memory")
#define CP_WAIT0()  asm volatile("cp.async.wait_group 0;\n" ::: "memory")

__device__ __forceinline__ float block_reduce_sum(float v, float* sh) {
    int lane = threadIdx.x & 31, wid = threadIdx.x >> 5;
    #pragma unroll
    for (int o = 16; o > 0; o >>= 1) v += __shfl_down_sync(0xffffffffu, v, o);
    if (lane == 0) sh[wid] = v;
    __syncthreads();
    float r = (threadIdx.x < (blockDim.x >> 5)) ? sh[threadIdx.x] : 0.0f;
    if (wid == 0) {
        #pragma unroll
        for (int o = 4; o > 0; o >>= 1) r += __shfl_down_sync(0xffffffffu, r, o);
        if (lane == 0) sh[0] = r;
    }
    __syncthreads();
    r = sh[0];
    __syncthreads();
    return r;
}

// pack 8 consecutive (f0 = k0..3, f1 = k4..7) into the permuted layout:
// out0 = {k0,k4,k1,k5}, out1 = {k2,k6,k3,k7}
__device__ __forceinline__ void perm_pack(const float4 f0, const float4 f1,
                                          float4& o0, float4& o1) {
    o0.x = f0.x; o0.y = f1.x; o0.z = f0.y; o0.w = f1.y;
    o1.x = f0.z; o1.y = f1.z; o1.z = f0.w; o1.w = f1.w;
}

// ---------------- round + permute (keys) ----------------
__global__ void round_perm_kernel(const float* __restrict__ in, float* __restrict__ out, int n8) {
    int i = blockIdx.x * blockDim.x + threadIdx.x;
    if (i >= n8) return;
    const float* p = in + (size_t)i * 8;
    float4 f0 = *(const float4*)p;
    float4 f1 = *(const float4*)(p + 4);
    f0.x = rnd_tf(f0.x); f0.y = rnd_tf(f0.y); f0.z = rnd_tf(f0.z); f0.w = rnd_tf(f0.w);
    f1.x = rnd_tf(f1.x); f1.y = rnd_tf(f1.y); f1.z = rnd_tf(f1.z); f1.w = rnd_tf(f1.w);
    float4 o0, o1;
    perm_pack(f0, f1, o0, o1);
    *(float4*)(out + (size_t)i * 8)     = o0;
    *(float4*)(out + (size_t)i * 8 + 4) = o1;
}

// ---------------- transpose + round + permute columns (vals) ----------------
__global__ void transpose_kernel(const float* __restrict__ in, float* __restrict__ out,
                                 int R, int C) {
    __shared__ float t[32][33];
    int x  = blockIdx.x * 32 + threadIdx.x;
    int y0 = blockIdx.y * 32;
    #pragma unroll
    for (int i = threadIdx.y; i < 32; i += 8)
        t[i][threadIdx.x] = in[(size_t)(y0 + i) * C + x];
    __syncthreads();
    int xo  = blockIdx.y * 32 + threadIdx.x;      // output column = k index
    int xo_p = (xo & ~7) | pos8(xo & 7);
    int yo0 = blockIdx.x * 32;
    #pragma unroll
    for (int i = threadIdx.y; i < 32; i += 8)
        out[(size_t)(yo0 + i) * R + xo_p] = rnd_tf(t[threadIdx.x][i]);
}

// ---------------- LayerNorm (rounded + permuted output), 128 threads ----------------
__global__ void ln_kernel(const float* __restrict__ x, const float* __restrict__ w,
                          const float* __restrict__ b, float* __restrict__ y) {
    __shared__ float sh[32];
    int row = blockIdx.x;
    int tid = threadIdx.x;
    const float* xr = x + (size_t)row * H_ + tid * 8;
    const float4 v0 = *(const float4*)xr;
    const float4 v1 = *(const float4*)(xr + 4);
    float s  = v0.x + v0.y + v0.z + v0.w + v1.x + v1.y + v1.z + v1.w;
    float sq = v0.x*v0.x + v0.y*v0.y + v0.z*v0.z + v0.w*v0.w
             + v1.x*v1.x + v1.y*v1.y + v1.z*v1.z + v1.w*v1.w;
    float S  = block_reduce_sum(s,  sh);
    float SQ = block_reduce_sum(sq, sh);
    float mu  = S * (1.0f / H_);
    float var = SQ * (1.0f / H_) - mu * mu;
    float inv = rsqrtf(var + 1e-5f);
    const float4 w0 = *(const float4*)(w + tid * 8);
    const float4 w1 = *(const float4*)(w + tid * 8 + 4);
    const float4 b0 = *(const float4*)(b + tid * 8);
    const float4 b1 = *(const float4*)(b + tid * 8 + 4);
    float4 f0, f1;
    f0.x = rnd_tf((v0.x - mu) * inv * w0.x + b0.x);
    f0.y = rnd_tf((v0.y - mu) * inv * w0.y + b0.y);
    f0.z = rnd_tf((v0.z - mu) * inv * w0.z + b0.z);
    f0.w = rnd_tf((v0.w - mu) * inv * w0.w + b0.w);
    f1.x = rnd_tf((v1.x - mu) * inv * w1.x + b1.x);
    f1.y = rnd_tf((v1.y - mu) * inv * w1.y + b1.y);
    f1.z = rnd_tf((v1.z - mu) * inv * w1.z + b1.z);
    f1.w = rnd_tf((v1.w - mu) * inv * w1.w + b1.w);
    float4 o0, o1;
    perm_pack(f0, f1, o0, o1);
    float* yr = y + (size_t)row * H_ + tid * 8;
    *(float4*)yr       = o0;
    *(float4*)(yr + 4) = o1;
}

// ---------------- gelu + L2-rownorm, single pass, permuted output, 128 threads ----------------
__global__ void rownorm_kernel(float* __restrict__ a, int cols) {
    __shared__ float sh[32];
    int row = blockIdx.x;
    int tid = threadIdx.x;
    float* ar = a + (size_t)row * cols;
    const int it = cols >> 10;           // 1 (cols=1024) or 4 (cols=4096)
    float g[32];
    float s = 0.0f;
    for (int i = 0; i < it; i++) {
        int c0 = i * 1024 + tid * 8;
        float4 f0 = *(const float4*)(ar + c0);
        float4 f1 = *(const float4*)(ar + c0 + 4);
        float* gi = g + i * 8;
        gi[0] = gelu_exact(f0.x); gi[1] = gelu_exact(f0.y);
        gi[2] = gelu_exact(f0.z); gi[3] = gelu_exact(f0.w);
        gi[4] = gelu_exact(f1.x); gi[5] = gelu_exact(f1.y);
        gi[6] = gelu_exact(f1.z); gi[7] = gelu_exact(f1.w);
        #pragma unroll
        for (int j = 0; j < 8; j++) s += gi[j] * gi[j];
    }
    float tot = block_reduce_sum(s, sh);
    float sc = sqrtf((float)cols) * rsqrtf(tot);
    for (int i = 0; i < it; i++) {
        int c0 = i * 1024 + tid * 8;
        float* gi = g + i * 8;
        float4 f0, f1;
        f0.x = rnd_tf(gi[0] * sc); f0.y = rnd_tf(gi[1] * sc);
        f0.z = rnd_tf(gi[2] * sc); f0.w = rnd_tf(gi[3] * sc);
        f1.x = rnd_tf(gi[4] * sc); f1.y = rnd_tf(gi[5] * sc);
        f1.z = rnd_tf(gi[6] * sc); f1.w = rnd_tf(gi[7] * sc);
        float4 o0, o1;
        perm_pack(f0, f1, o0, o1);
        *(float4*)(ar + c0)     = o0;
        *(float4*)(ar + c0 + 4) = o1;
    }
}

// ---------------- TF32 GEMM: CTA 128x128x32, 4 warps, warp tile 64x64 ----------------
// C[M,N] = alpha * A[M,K] @ B[N,K]^T (+ Res).  A,B pre-rounded tf32 and k-pair-interleaved.
#define KPAD 40
#define TSZ  (128 * KPAD)

__global__ void __launch_bounds__(128) ntgemm_kernel(
    const float* __restrict__ A, const float* __restrict__ Bm,
    const float* __restrict__ Res, float* __restrict__ C,
    int M, int N, int K, float alpha)
{
    extern __shared__ float sh[];
    float* As = sh;             // [2][TSZ]
    float* Bs = sh + 2 * TSZ;   // [2][TSZ]

    const int bx = blockIdx.x, by = blockIdx.y;
    const int tid = threadIdx.x;
    const int lane = tid & 31, w = tid >> 5;
    const int wm = w & 1, wn = w >> 1;     // 2x2 warps, 64m x 64n each
    const int lr = lane >> 2, lc = lane & 3;

    float acc[4][8][4];
    #pragma unroll
    for (int i = 0; i < 4; i++)
        #pragma unroll
        for (int j = 0; j < 8; j++)
            #pragma unroll
            for (int t = 0; t < 4; t++) acc[i][j][t] = 0.0f;

    const int iters = K >> 5;
    const int r_ld = tid >> 3;    // 0..15
    const int k4   = tid & 7;     // float4 slot in k (0..7)

    auto load_tile = [&](int t, int buf) {
        int k0 = t << 5;
        #pragma unroll
        for (int i = 0; i < 8; i++) {
            int row = r_ld + i * 16;
            const float* src = A + (size_t)(by * 128 + row) * K + k0 + k4 * 4;
            uint32_t dst = (uint32_t)__cvta_generic_to_shared(As + buf * TSZ + row * KPAD + k4 * 4);
            cp_async16(dst, src);
        }
        #pragma unroll
        for (int i = 0; i < 8; i++) {
            int row = r_ld + i * 16;
            const float* src = Bm + (size_t)(bx * 128 + row) * K + k0 + k4 * 4;
            uint32_t dst = (uint32_t)__cvta_generic_to_shared(Bs + buf * TSZ + row * KPAD + k4 * 4);
            cp_async16(dst, src);
        }
    };

    load_tile(0, 0);
    CP_COMMIT();

    int buf = 0;
    for (int t = 0; t < iters; t++) {
        CP_WAIT0();
        __syncthreads();
        if (t + 1 < iters) {
            load_tile(t + 1, buf ^ 1);
            CP_COMMIT();
        }
        const float* Ab = As + buf * TSZ;
        const float* Bb = Bs + buf * TSZ;
        #pragma unroll
        for (int ks = 0; ks < 4; ks++) {
            int kb = ks * 8 + lc * 2;
            uint32_t afr[4][4];
            #pragma unroll
            for (int mt = 0; mt < 4; mt++) {
                const float* ap = Ab + (wm * 64 + mt * 16 + lr) * KPAD + kb;
                uint2 p0 = *(const uint2*)ap;
                uint2 p1 = *(const uint2*)(ap + 8 * KPAD);
                afr[mt][0] = __float_as_uint(__uint_as_float(p0.x));
                afr[mt][1] = p1.x; afr[mt][2] = p0.y; afr[mt][3] = p1.y;
                afr[mt][0] = p0.x;
            }
            #pragma unroll
            for (int nt = 0; nt < 8; nt++) {
                const float* bp = Bb + (wn * 64 + nt * 8 + lr) * KPAD + kb;
                uint2 bb = *(const uint2*)bp;
                uint32_t bfr[2] = {bb.x, bb.y};
                #pragma unroll
                for (int mt = 0; mt < 4; mt++)
                    mma_tf32(acc[mt][nt], afr[mt], bfr);
            }
        }
        buf ^= 1;
    }

    // epilogue (+ optional residual)
    #pragma unroll
    for (int mt = 0; mt < 4; mt++) {
        int r0 = by * 128 + wm * 64 + mt * 16 + lr;
        #pragma unroll
        for (int nt = 0; nt < 8; nt++) {
            int c = bx * 128 + wn * 64 + nt * 8 + 2 * lc;
            float2 lo = {acc[mt][nt][0] * alpha, acc[mt][nt][1] * alpha};
            float2 hi = {acc[mt][nt][2] * alpha, acc[mt][nt][3] * alpha};
            if (Res) {
                float2 rlo = *(const float2*)(Res + (size_t)r0 * N + c);
                float2 rhi = *(const float2*)(Res + (size_t)(r0 + 8) * N + c);
                lo.x += rlo.x; lo.y += rlo.y; hi.x += rhi.x; hi.y += rhi.y;
            }
            *(float2*)(C + (size_t)r0 * N + c)       = lo;
            *(float2*)(C + (size_t)(r0 + 8) * N + c) = hi;
        }
    }
}

// ---------------- RoPE ----------------
__global__ void rope_kernel(float* __restrict__ q, float* __restrict__ k) {
    int idx = blockIdx.x * blockDim.x + threadIdx.x;
    if (idx >= T_ * NH_) return;
    int h  = idx & (NH_ - 1);
    int bs = idx >> 4;
    int s  = bs & (S_ - 1);
    float* qp = q + (size_t)bs * H_ + h * HD_;
    float* kp = k + (size_t)bs * H_ + h * HD_;
    float qv[ROT_], kv[ROT_];
    #pragma unroll
    for (int i = 0; i < ROT_; i++) { qv[i] = qp[i]; kv[i] = kp[i]; }
    #pragma unroll
    for (int i = 0; i < ROT_ / 2; i++) {
        double invf = pow(10000.0, -(double)(2 * i) / (double)ROT_);
        double ang = (double)s * invf;
        float c  = (float)cos(ang);
        float sn = (float)sin(ang);
        float q0 = qv[i], q1 = qv[i + 8];
        qv[i]     = q0 * c - q1 * sn;
        qv[i + 8] = q1 * c + q0 * sn;
        float k0 = kv[i], k1 = kv[i + 8];
        kv[i]     = k0 * c - k1 * sn;
        kv[i + 8] = k1 * c + k0 * sn;
    }
    #pragma unroll
    for (int i = 0; i < ROT_; i++) { qp[i] = qv[i]; kp[i] = kv[i]; }
}

// ---------------- fused causal attention (tf32 mma, single pass) ----------------
// O = (sum gelu(qk/8)*V) * sqrt(S)/sqrt(sum gelu^2). Output rounded + k-permuted.
#define ATPAD 68
__global__ void __launch_bounds__(128, 2) attn_kernel(
    const float* __restrict__ Q, const float* __restrict__ K,
    const float* __restrict__ V, float* __restrict__ O)
{
    extern __shared__ uint32_t sm[];
    uint32_t* Qs = sm;
    uint32_t* Ks = Qs + 64 * ATPAD;
    uint32_t* Vs = Ks + 64 * ATPAD;
    uint32_t* Ss = Vs + 64 * ATPAD;

    const int qt  = blockIdx.x;
    const int bh  = blockIdx.y;
    const int b   = bh >> 4, h = bh & 15;
    const int tid = threadIdx.x;
    const int lane = tid & 31, w = tid >> 5;
    const int lr = lane >> 2, lc = lane & 3;
    const size_t base = (size_t)(b * S_) * H_ + h * HD_;

    #pragma unroll
    for (int it = 0; it < 4; it++) {
        int slot = tid + it * 128;
        int r = slot >> 3, g = slot & 7;
        const float* src = Q + base + (size_t)(qt * 64 + r) * H_ + g * 8;
        float4 f0 = *(const float4*)src;
        float4 f1 = *(const float4*)(src + 4);
        uint32_t* p = Qs + r * ATPAD + g * 8;
        uint4 u;
        u.x = f2tf(f0.x); u.y = f2tf(f1.x); u.z = f2tf(f0.y); u.w = f2tf(f1.y);
        *(uint4*)p = u;
        u.x = f2tf(f0.z); u.y = f2tf(f1.z); u.z = f2tf(f0.w); u.w = f2tf(f1.w);
        *(uint4*)(p + 4) = u;
    }

    float oacc[8][4];
    #pragma unroll
    for (int i = 0; i < 8; i++)
        #pragma unroll
        for (int j = 0; j < 4; j++) oacc[i][j] = 0.0f;
    float n2lo = 0.0f, n2hi = 0.0f;

    for (int kt = 0; kt <= qt; kt++) {
        __syncthreads();
        #pragma unroll
        for (int it = 0; it < 4; it++) {
            int slot = tid + it * 128;
            int r = slot >> 3, g = slot & 7;
            const float* srck = K + base + (size_t)(kt * 64 + r) * H_ + g * 8;
            float4 f0 = *(const float4*)srck;
            float4 f1 = *(const float4*)(srck + 4);
            uint32_t* p = Ks + r * ATPAD + g * 8;
            uint4 u;
            u.x = f2tf(f0.x); u.y = f2tf(f1.x); u.z = f2tf(f0.y); u.w = f2tf(f1.y);
            *(uint4*)p = u;
            u.x = f2tf(f0.z); u.y = f2tf(f1.z); u.z = f2tf(f0.w); u.w = f2tf(f1.w);
            *(uint4*)(p + 4) = u;
            const float* srcv = V + base + (size_t)(kt * 64 + r) * H_ + g * 8;
            float4 v0 = *(const float4*)srcv;
            float4 v1 = *(const float4*)(srcv + 4);
            uint32_t* pv = Vs + r * ATPAD + g * 8;
            uint4 uv;
            uv.x = f2tf(v0.x); uv.y = f2tf(v0.y); uv.z = f2tf(v0.z); uv.w = f2tf(v0.w);
            *(uint4*)pv = uv;
            uv.x = f2tf(v1.x); uv.y = f2tf(v1.y); uv.z = f2tf(v1.z); uv.w = f2tf(v1.w);
            *(uint4*)(pv + 4) = uv;
        }
        __syncthreads();

        float sacc[8][4];
        #pragma unroll
        for (int i = 0; i < 8; i++)
            #pragma unroll
            for (int j = 0; j < 4; j++) sacc[i][j] = 0.0f;
        #pragma unroll
        for (int ks = 0; ks < 8; ks++) {
            const uint32_t* ap = Qs + (w * 16 + lr) * ATPAD + ks * 8 + lc * 2;
            uint2 p0 = *(const uint2*)ap;
            uint2 p1 = *(const uint2*)(ap + 8 * ATPAD);
            uint32_t a[4] = {p0.x, p1.x, p0.y, p1.y};
            #pragma unroll
            for (int nt = 0; nt < 8; nt++) {
                const uint32_t* bp = Ks + (nt * 8 + lr) * ATPAD + ks * 8 + lc * 2;
                uint2 bb = *(const uint2*)bp;
                uint32_t bfr[2] = {bb.x, bb.y};
                mma_tf32(sacc[nt], a, bfr);
            }
        }

        int q0 = qt * 64 + w * 16 + lr;
        int t7a = 2 * lc, t7b = 2 * lc + 1;
        int oa = pos8(t7a), ob = pos8(t7b);
        #pragma unroll
        for (int nt = 0; nt < 8; nt++) {
            int k0c = kt * 64 + nt * 8 + 2 * lc;
            float g0 = (k0c     <= q0)     ? gelu_exact(sacc[nt][0] * 0.125f) : 0.0f;
            float g1 = (k0c + 1 <= q0)     ? gelu_exact(sacc[nt][1] * 0.125f) : 0.0f;
            float g2 = (k0c     <= q0 + 8) ? gelu_exact(sacc[nt][2] * 0.125f) : 0.0f;
            float g3 = (k0c + 1 <= q0 + 8) ? gelu_exact(sacc[nt][3] * 0.125f) : 0.0f;
            n2lo += g0 * g0 + g1 * g1;
            n2hi += g2 * g2 + g3 * g3;
            Ss[(w * 16 + lr)     * ATPAD + nt * 8 + oa] = f2tf(g0);
            Ss[(w * 16 + lr)     * ATPAD + nt * 8 + ob] = f2tf(g1);
            Ss[(w * 16 + lr + 8) * ATPAD + nt * 8 + oa] = f2tf(g2);
            Ss[(w * 16 + lr + 8) * ATPAD + nt * 8 + ob] = f2tf(g3);
        }
        __syncwarp();

        #pragma unroll
        for (int ks = 0; ks < 8; ks++) {
            const uint32_t* ap = Ss + (w * 16 + lr) * ATPAD + ks * 8 + lc * 2;
            uint2 p0 = *(const uint2*)ap;
            uint2 p1 = *(const uint2*)(ap + 8 * ATPAD);
            uint32_t a[4] = {p0.x, p1.x, p0.y, p1.y};
            #pragma unroll
            for (int nt = 0; nt < 8; nt++) {
                uint32_t bfr[2];
                bfr[0] = Vs[(ks * 8 + lc)     * ATPAD + nt * 8 + lr];
                bfr[1] = Vs[(ks * 8 + lc + 4) * ATPAD + nt * 8 + lr];
                mma_tf32(oacc[nt], a, bfr);
            }
        }
    }

    n2lo += __shfl_xor_sync(0xffffffffu, n2lo, 1);
    n2lo += __shfl_xor_sync(0xffffffffu, n2lo, 2);
    n2hi += __shfl_xor_sync(0xffffffffu, n2hi, 1);
    n2hi += __shfl_xor_sync(0xffffffffu, n2hi, 2);

    const float sqS = 45.25483399593904f;
    float sclo = sqS * rsqrtf(n2lo);
    float schi = sqS * rsqrtf(n2hi);

    // store rounded + k-permuted (feeds proj GEMM as A)
    int r0 = qt * 64 + w * 16 + lr;
    int c0a = pos8(2 * lc), c0b = pos8(2 * lc + 1);
    #pragma unroll
    for (int nt = 0; nt < 8; nt++) {
        float* orow0 = (float*)(O + base + (size_t)r0 * H_ + nt * 8);
        float* orow1 = (float*)(O + base + (size_t)(r0 + 8) * H_ + nt * 8);
        orow0[c0a] = rnd_tf(oacc[nt][0] * sclo);
        orow0[c0b] = rnd_tf(oacc[nt][1] * sclo);
        orow1[c0a] = rnd_tf(oacc[nt][2] * schi);
        orow1[c0b] = rnd_tf(oacc[nt][3] * schi);
    }
}

// ---------------- launch ----------------
extern "C" void kernel_launch(void* const* d_in, const int* in_sizes, int n_in,
                              void* d_out, int out_size) {
    const float* x        = (const float*)d_in[0];
    const float* ln1_w    = (const float*)d_in[1];
    const float* ln1_b    = (const float*)d_in[2];
    const float* ln2_w    = (const float*)d_in[3];
    const float* ln2_b    = (const float*)d_in[4];
    const float* q_key    = (const float*)d_in[5];
    const float* q_val    = (const float*)d_in[6];
    const float* k_key    = (const float*)d_in[7];
    const float* k_val    = (const float*)d_in[8];
    const float* v_key    = (const float*)d_in[9];
    const float* v_val    = (const float*)d_in[10];
    const float* proj_key = (const float*)d_in[11];
    const float* proj_val = (const float*)d_in[12];
    const float* ffn_key  = (const float*)d_in[13];
    const float* ffn_val  = (const float*)d_in[14];
    float* out = (float*)d_out;

    float *p_xn, *p_big, *p_q, *p_k, *p_v, *p_o, *p_x1;
    float *p_qvT, *p_kvT, *p_vvT, *p_pvT, *p_fvT;
    float *p_qkR, *p_kkR, *p_vkR, *p_pkR, *p_fkR;
    cudaGetSymbolAddress((void**)&p_xn,  d_xn);
    cudaGetSymbolAddress((void**)&p_big, d_big);
    cudaGetSymbolAddress((void**)&p_q,   d_q);
    cudaGetSymbolAddress((void**)&p_k,   d_k);
    cudaGetSymbolAddress((void**)&p_v,   d_v);
    cudaGetSymbolAddress((void**)&p_o,   d_o);
    cudaGetSymbolAddress((void**)&p_x1,  d_x1);
    cudaGetSymbolAddress((void**)&p_qvT, d_qvT);
    cudaGetSymbolAddress((void**)&p_kvT, d_kvT);
    cudaGetSymbolAddress((void**)&p_vvT, d_vvT);
    cudaGetSymbolAddress((void**)&p_pvT, d_pvT);
    cudaGetSymbolAddress((void**)&p_fvT, d_fvT);
    cudaGetSymbolAddress((void**)&p_qkR, d_qkR);
    cudaGetSymbolAddress((void**)&p_kkR, d_kkR);
    cudaGetSymbolAddress((void**)&p_vkR, d_vkR);
    cudaGetSymbolAddress((void**)&p_pkR, d_pkR);
    cudaGetSymbolAddress((void**)&p_fkR, d_fkR);

    const float sqrtH = 32.0f;
    dim3 g_small(H_ / 128, T_ / 128);       // (8, 32)
    dim3 g_ffn1(FFN_ / 128, T_ / 128);      // (32, 32)
    dim3 tthr(32, 8);
    dim3 tgrd(H_ / 32, H_ / 32);
    dim3 tgrd_f(H_ / 32, FFN_ / 32);

    const int smem_g = 4 * TSZ * 4;         // 81920
    cudaFuncSetAttribute(ntgemm_kernel, cudaFuncAttributeMaxDynamicSharedMemorySize, smem_g);

    // preprocess weights
    const int n8_hh = H_ * H_ / 8, n8_fh = FFN_ * H_ / 8;
    round_perm_kernel<<<(n8_hh + 255) / 256, 256>>>(q_key,    p_qkR, n8_hh);
    round_perm_kernel<<<(n8_hh + 255) / 256, 256>>>(k_key,    p_kkR, n8_hh);
    round_perm_kernel<<<(n8_hh + 255) / 256, 256>>>(v_key,    p_vkR, n8_hh);
    round_perm_kernel<<<(n8_hh + 255) / 256, 256>>>(proj_key, p_pkR, n8_hh);
    round_perm_kernel<<<(n8_fh + 255) / 256, 256>>>(ffn_key,  p_fkR, n8_fh);
    transpose_kernel<<<tgrd,   tthr>>>(q_val,    p_qvT, H_,   H_);
    transpose_kernel<<<tgrd,   tthr>>>(k_val,    p_kvT, H_,   H_);
    transpose_kernel<<<tgrd,   tthr>>>(v_val,    p_vvT, H_,   H_);
    transpose_kernel<<<tgrd,   tthr>>>(proj_val, p_pvT, H_,   H_);
    transpose_kernel<<<tgrd_f, tthr>>>(ffn_val,  p_fvT, FFN_, H_);

    ln_kernel<<<T_, 128>>>(x, ln1_w, ln1_b, p_xn);

    ntgemm_kernel<<<g_small, 128, smem_g>>>(p_xn, p_qkR, nullptr, p_big, T_, H_, H_, sqrtH);
    rownorm_kernel<<<T_, 128>>>(p_big, H_);
    ntgemm_kernel<<<g_small, 128, smem_g>>>(p_big, p_qvT, nullptr, p_q, T_, H_, H_, 1.0f);

    ntgemm_kernel<<<g_small, 128, smem_g>>>(p_xn, p_kkR, nullptr, p_big, T_, H_, H_, sqrtH);
    rownorm_kernel<<<T_, 128>>>(p_big, H_);
    ntgemm_kernel<<<g_small, 128, smem_g>>>(p_big, p_kvT, nullptr, p_k, T_, H_, H_, 1.0f);

    ntgemm_kernel<<<g_small, 128, smem_g>>>(p_xn, p_vkR, nullptr, p_big, T_, H_, H_, sqrtH);
    rownorm_kernel<<<T_, 128>>>(p_big, H_);
    ntgemm_kernel<<<g_small, 128, smem_g>>>(p_big, p_vvT, nullptr, p_v, T_, H_, H_, 1.0f);

    rope_kernel<<<(T_ * NH_) / 256, 256>>>(p_q, p_k);

    {
        int smem = 4 * 64 * ATPAD * sizeof(float);
        cudaFuncSetAttribute(attn_kernel, cudaFuncAttributeMaxDynamicSharedMemorySize, smem);
        dim3 grid(S_ / 64, B_ * NH_);
        attn_kernel<<<grid, 128, smem>>>(p_q, p_k, p_v, p_o);
    }

    // proj pattention + fused residual
    ntgemm_kernel<<<g_small, 128, smem_g>>>(p_o, p_pkR, nullptr, p_big, T_, H_, H_, sqrtH);
    rownorm_kernel<<<T_, 128>>>(p_big, H_);
    ntgemm_kernel<<<g_small, 128, smem_g>>>(p_big, p_pvT, x, p_x1, T_, H_, H_, 1.0f);

    // ffn pattention + fused residual
    ln_kernel<<<T_, 128>>>(p_x1, ln2_w, ln2_b, p_xn);
    ntgemm_kernel<<<g_ffn1, 128, smem_g>>>(p_xn, p_fkR, nullptr, p_big, T_, FFN_, H_, sqrtH);
    rownorm_kernel<<<T_, 128>>>(p_big, FFN_);
    ntgemm_kernel<<<g_small, 128, smem_g>>>(p_big, p_fvT, p_x1, out, T_, H_, FFN_, 1.0f);
}

// round 7
// speedup vs baseline: 1.1906x; 1.1906x over previous
#include <cuda_runtime.h>
#include <cuda_fp16.h>
#include <math.h>
#include <stdint.h>

// ---------------- problem constants ----------------
#define B_   2
#define S_   2048
#define H_   1024
#define NH_  16
#define HD_  64
#define T_   (B_*S_)      // 4096 tokens
#define FFN_ 4096
#define ROT_ 16

// ---------------- static scratch ----------------
__device__ float  d_big[T_*FFN_];     // gemm1 outputs (fp32, plain)
__device__ float  d_q  [T_*H_];
__device__ float  d_k  [T_*H_];
__device__ float  d_v  [T_*H_];
__device__ float  d_x1 [T_*H_];
__device__ __half d_xnh [T_*H_];      // ln outputs (half, k-permuted)
__device__ __half d_bigh[T_*FFN_];    // rownorm outputs (half, k-permuted)
__device__ __half d_oh  [T_*H_];      // attention output (half, k-permuted)
// preprocessed weights (half, k-permuted; vals also transposed)
__device__ __half d_qkh[H_*H_];
__device__ __half d_kkh[H_*H_];
__device__ __half d_vkh[H_*H_];
__device__ __half d_pkh[H_*H_];
__device__ __half d_fkh[FFN_*H_];
__device__ __half d_qvh[H_*H_];
__device__ __half d_kvh[H_*H_];
__device__ __half d_vvh[H_*H_];
__device__ __half d_pvh[H_*H_];
__device__ __half d_fvh[H_*FFN_];

// ---------------- helpers ----------------
__device__ __forceinline__ float gelu_exact(float x) {
    return 0.5f * x * (1.0f + erff(x * 0.7071067811865475f));
}
__device__ __forceinline__ uint32_t f2tf(float f) {
    uint32_t u;
    asm("cvt.rna.tf32.f32 %0, %1;" : "=r"(u) : "f"(f));
    return u;
}
// half-pair permutation within a 16-k group: half2-unit u (0..7) -> uint slot 2*(u&3)+(u>>2)
__device__ __forceinline__ int hperm(int u) { return 2 * (u & 3) + (u >> 2); }

__device__ __forceinline__ uint32_t h2u(float a, float b) {
    __half2 h = __floats2half2_rn(a, b);
    return *(uint32_t*)&h;
}
// pack 16 consecutive k-values into permuted half layout (2 uint4)
__device__ __forceinline__ void pack16(const float* f, uint4& lo, uint4& hi) {
    lo.x = h2u(f[0], f[1]);   lo.y = h2u(f[8], f[9]);
    lo.z = h2u(f[2], f[3]);   lo.w = h2u(f[10], f[11]);
    hi.x = h2u(f[4], f[5]);   hi.y = h2u(f[12], f[13]);
    hi.z = h2u(f[6], f[7]);   hi.w = h2u(f[14], f[15]);
}

__device__ __forceinline__ void mma_f16(float* d, const uint32_t* a, const uint32_t* b) {
    asm volatile(
        "mma.sync.aligned.m16n8k16.row.col.f32.f16.f16.f32 "
        "{%0,%1,%2,%3}, {%4,%5,%6,%7}, {%8,%9}, {%0,%1,%2,%3};\n"
        : "+f"(d[0]), "+f"(d[1]), "+f"(d[2]), "+f"(d[3])
        : "r"(a[0]), "r"(a[1]), "r"(a[2]), "r"(a[3]), "r"(b[0]), "r"(b[1]));
}
__device__ __forceinline__ void mma_tf32(float* d, const uint32_t* a, const uint32_t* b) {
    asm volatile(
        "mma.sync.aligned.m16n8k8.row.col.f32.tf32.tf32.f32 "
        "{%0,%1,%2,%3}, {%4,%5,%6,%7}, {%8,%9}, {%0,%1,%2,%3};\n"
        : "+f"(d[0]), "+f"(d[1]), "+f"(d[2]), "+f"(d[3])
        : "r"(a[0]), "r"(a[1]), "r"(a[2]), "r"(a[3]), "r"(b[0]), "r"(b[1]));
}
__device__ __forceinline__ void cp_async16(uint32_t smem_addr, const void* gptr) {
    asm volatile("cp.async.cg.shared.global [%0], [%1], 16;\n" :: "r"(smem_addr), "l"(gptr));
}
#define CP_COMMIT() asm volatile("cp.async.commit_group;\n" ::: "memory")
#define CP_WAIT(n)  asm volatile("cp.async.wait_group %0;\n" :: "n"(n) : "memory")

__device__ __forceinline__ float block_reduce_sum(float v, float* sh) {
    int lane = threadIdx.x & 31, wid = threadIdx.x >> 5;
    #pragma unroll
    for (int o = 16; o > 0; o >>= 1) v += __shfl_down_sync(0xffffffffu, v, o);
    if (lane == 0) sh[wid] = v;
    __syncthreads();
    float r = (threadIdx.x < (blockDim.x >> 5)) ? sh[threadIdx.x] : 0.0f;
    if (wid == 0) {
        #pragma unroll
        for (int o = 4; o > 0; o >>= 1) r += __shfl_down_sync(0xffffffffu, r, o);
        if (lane == 0) sh[0] = r;
    }
    __syncthreads();
    r = sh[0];
    __syncthreads();
    return r;
}

// ---------------- weight prep: fp32 -> half permuted ----------------
__global__ void round_perm_kernel(const float* __restrict__ in, __half* __restrict__ out, int n16) {
    int i = blockIdx.x * blockDim.x + threadIdx.x;
    if (i >= n16) return;
    const float* p = in + (size_t)i * 16;
    float f[16];
    #pragma unroll
    for (int j = 0; j < 16; j += 4) {
        float4 v = *(const float4*)(p + j);
        f[j] = v.x; f[j+1] = v.y; f[j+2] = v.z; f[j+3] = v.w;
    }
    uint4 lo, hi;
    pack16(f, lo, hi);
    uint4* o = (uint4*)(out + (size_t)i * 16);
    o[0] = lo; o[1] = hi;
}

// ---------------- transpose + half + permuted columns (vals) ----------------
__global__ void transpose_kernel(const float* __restrict__ in, __half* __restrict__ out,
                                 int R, int C) {
    __shared__ float t[32][33];
    int x  = blockIdx.x * 32 + threadIdx.x;
    int y0 = blockIdx.y * 32;
    #pragma unroll
    for (int i = threadIdx.y; i < 32; i += 8)
        t[i][threadIdx.x] = in[(size_t)(y0 + i) * C + x];
    __syncthreads();
    int xo = blockIdx.y * 32 + threadIdx.x;        // output column = k index
    int r  = xo & 15;
    int xo_p = (xo & ~15) | (2 * hperm(r >> 1) + (r & 1));
    int yo0 = blockIdx.x * 32;
    #pragma unroll
    for (int i = threadIdx.y; i < 32; i += 8)
        out[(size_t)(yo0 + i) * R + xo_p] = __float2half(t[threadIdx.x][i]);
}

// ---------------- LayerNorm: fp32 in -> half permuted out, 64 threads ----------------
__global__ void ln_kernel(const float* __restrict__ x, const float* __restrict__ w,
                          const float* __restrict__ b, __half* __restrict__ y) {
    __shared__ float sh[32];
    int row = blockIdx.x;
    int tid = threadIdx.x;
    const float* xr = x + (size_t)row * H_ + tid * 16;
    float f[16];
    float s = 0.0f, sq = 0.0f;
    #pragma unroll
    for (int j = 0; j < 16; j += 4) {
        float4 v = *(const float4*)(xr + j);
        f[j] = v.x; f[j+1] = v.y; f[j+2] = v.z; f[j+3] = v.w;
        s  += v.x + v.y + v.z + v.w;
        sq += v.x*v.x + v.y*v.y + v.z*v.z + v.w*v.w;
    }
    float S  = block_reduce_sum(s,  sh);
    float SQ = block_reduce_sum(sq, sh);
    float mu  = S * (1.0f / H_);
    float var = SQ * (1.0f / H_) - mu * mu;
    float inv = rsqrtf(var + 1e-5f);
    const float* wr = w + tid * 16;
    const float* br = b + tid * 16;
    #pragma unroll
    for (int j = 0; j < 16; j++)
        f[j] = (f[j] - mu) * inv * wr[j] + br[j];
    uint4 lo, hi;
    pack16(f, lo, hi);
    uint4* o = (uint4*)(y + (size_t)row * H_ + tid * 16);
    o[0] = lo; o[1] = hi;
}

// ---------------- gelu + L2-rownorm: fp32 in -> half permuted out ----------------
template <int NT>
__global__ void rownorm_kernel(const float* __restrict__ in, __half* __restrict__ out, int cols) {
    __shared__ float sh[32];
    int row = blockIdx.x;
    int tid = threadIdx.x;
    const float* ar = in + (size_t)row * cols + tid * 16;
    float g[16];
    float s = 0.0f;
    #pragma unroll
    for (int j = 0; j < 16; j += 4) {
        float4 v = *(const float4*)(ar + j);
        g[j]   = gelu_exact(v.x); g[j+1] = gelu_exact(v.y);
        g[j+2] = gelu_exact(v.z); g[j+3] = gelu_exact(v.w);
        s += g[j]*g[j] + g[j+1]*g[j+1] + g[j+2]*g[j+2] + g[j+3]*g[j+3];
    }
    float tot = block_reduce_sum(s, sh);
    float sc = sqrtf((float)cols) * rsqrtf(tot);
    #pragma unroll
    for (int j = 0; j < 16; j++) g[j] *= sc;
    uint4 lo, hi;
    pack16(g, lo, hi);
    uint4* o = (uint4*)(out + (size_t)row * cols + tid * 16);
    o[0] = lo; o[1] = hi;
}

// ---------------- FP16 tensor-core GEMM, NT, 128x128x32, cp.async 2-stage ----------------
// C[M,N] = alpha * A[M,K] @ B[N,K]^T (+ Res).  A,B are half, k-pair-permuted.
// smem rows: 8 uint2 data + 4 pad = 12 uint2 (96B) -> frag LDS.64 conflict-free.
#define HSTR 12
#define HTSZ (128 * HSTR)

__global__ void __launch_bounds__(256) hgemm_kernel(
    const __half* __restrict__ A, const __half* __restrict__ Bm,
    const float* __restrict__ Res, float* __restrict__ C,
    int M, int N, int K, float alpha)
{
    extern __shared__ uint2 sh2[];
    uint2* As = sh2;              // [2][HTSZ]
    uint2* Bs = sh2 + 2 * HTSZ;   // [2][HTSZ]

    const int bx = blockIdx.x, by = blockIdx.y;
    const int tid = threadIdx.x;
    const int lane = tid & 31, w = tid >> 5;
    const int wm = w & 3, wn = w >> 2;          // 4x2 warps; warp tile 32m x 64n
    const int lr = lane >> 2, lc = lane & 3;

    float acc[2][8][4];
    #pragma unroll
    for (int i = 0; i < 2; i++)
        #pragma unroll
        for (int j = 0; j < 8; j++)
            #pragma unroll
            for (int t = 0; t < 4; t++) acc[i][j][t] = 0.0f;

    const int iters = K >> 5;
    const int r_ld = tid >> 1;          // 0..127
    const int c2   = (tid & 1) * 2;     // chunk 0/2 (each chunk = 16B = 8 halves)

    auto load_tile = [&](int t, int buf) {
        int k0 = t << 5;
        const __half* srcA = A + (size_t)(by * 128 + r_ld) * K + k0 + c2 * 8;
        uint32_t dA = (uint32_t)__cvta_generic_to_shared(As + buf * HTSZ + r_ld * HSTR + c2 * 2);
        cp_async16(dA,      srcA);
        cp_async16(dA + 16, srcA + 8);
        const __half* srcB = Bm + (size_t)(bx * 128 + r_ld) * K + k0 + c2 * 8;
        uint32_t dB = (uint32_t)__cvta_generic_to_shared(Bs + buf * HTSZ + r_ld * HSTR + c2 * 2);
        cp_async16(dB,      srcB);
        cp_async16(dB + 16, srcB + 8);
    };

    load_tile(0, 0);
    CP_COMMIT();

    int buf = 0;
    for (int t = 0; t < iters; t++) {
        if (t + 1 < iters) {
            load_tile(t + 1, buf ^ 1);
            CP_COMMIT();
            CP_WAIT(1);
        } else {
            CP_WAIT(0);
        }
        __syncthreads();

        const uint2* Ab = As + buf * HTSZ;
        const uint2* Bb = Bs + buf * HTSZ;
        #pragma unroll
        for (int ks = 0; ks < 2; ks++) {            // two k16 steps
            uint32_t afr[2][4];
            #pragma unroll
            for (int mt = 0; mt < 2; mt++) {
                const uint2* ap = Ab + (wm * 32 + mt * 16 + lr) * HSTR + ks * 4 + lc;
                uint2 p0 = ap[0];
                uint2 p1 = ap[8 * HSTR];
                afr[mt][0] = p0.x; afr[mt][1] = p1.x;
                afr[mt][2] = p0.y; afr[mt][3] = p1.y;
            }
            #pragma unroll
            for (int nt = 0; nt < 8; nt++) {
                const uint2* bp = Bb + (wn * 64 + nt * 8 + lr) * HSTR + ks * 4 + lc;
                uint2 bb = bp[0];
                uint32_t bfr[2] = {bb.x, bb.y};
                mma_f16(acc[0][nt], afr[0], bfr);
                mma_f16(acc[1][nt], afr[1], bfr);
            }
        }
        buf ^= 1;
        __syncthreads();
    }

    // epilogue (+ optional residual), fp32 plain output
    #pragma unroll
    for (int mt = 0; mt < 2; mt++) {
        int r0 = by * 128 + wm * 32 + mt * 16 + lr;
        #pragma unroll
        for (int nt = 0; nt < 8; nt++) {
            int c = bx * 128 + wn * 64 + nt * 8 + 2 * lc;
            float2 lo = {acc[mt][nt][0] * alpha, acc[mt][nt][1] * alpha};
            float2 hi = {acc[mt][nt][2] * alpha, acc[mt][nt][3] * alpha};
            if (Res) {
                float2 rlo = *(const float2*)(Res + (size_t)r0 * N + c);
                float2 rhi = *(const float2*)(Res + (size_t)(r0 + 8) * N + c);
                lo.x += rlo.x; lo.y += rlo.y; hi.x += rhi.x; hi.y += rhi.y;
            }
            *(float2*)(C + (size_t)r0 * N + c)       = lo;
            *(float2*)(C + (size_t)(r0 + 8) * N + c) = hi;
        }
    }
}

// ---------------- RoPE (fp32 q,k in place) ----------------
__global__ void rope_kernel(float* __restrict__ q, float* __restrict__ k) {
    int idx = blockIdx.x * blockDim.x + threadIdx.x;
    if (idx >= T_ * NH_) return;
    int h  = idx & (NH_ - 1);
    int bs = idx >> 4;
    int s  = bs & (S_ - 1);
    float* qp = q + (size_t)bs * H_ + h * HD_;
    float* kp = k + (size_t)bs * H_ + h * HD_;
    float qv[ROT_], kv[ROT_];
    #pragma unroll
    for (int i = 0; i < ROT_; i++) { qv[i] = qp[i]; kv[i] = kp[i]; }
    #pragma unroll
    for (int i = 0; i < ROT_ / 2; i++) {
        double invf = pow(10000.0, -(double)(2 * i) / (double)ROT_);
        double ang = (double)s * invf;
        float c  = (float)cos(ang);
        float sn = (float)sin(ang);
        float q0 = qv[i], q1 = qv[i + 8];
        qv[i]     = q0 * c - q1 * sn;
        qv[i + 8] = q1 * c + q0 * sn;
        float k0 = kv[i], k1 = kv[i + 8];
        kv[i]     = k0 * c - k1 * sn;
        kv[i + 8] = k1 * c + k0 * sn;
    }
    #pragma unroll
    for (int i = 0; i < ROT_; i++) { qp[i] = qv[i]; kp[i] = kv[i]; }
}

// ---------------- fused causal attention (tf32 mma, single pass) ----------------
// fp32 Q,K,V in (plain layout); half k-permuted O out.
#define ATPAD 68
__global__ void __launch_bounds__(128, 2) attn_kernel(
    const float* __restrict__ Q, const float* __restrict__ K,
    const float* __restrict__ V, __half* __restrict__ O)
{
    extern __shared__ uint32_t sm[];
    uint32_t* Qs = sm;
    uint32_t* Ks = Qs + 64 * ATPAD;
    uint32_t* Vs = Ks + 64 * ATPAD;
    uint32_t* Ss = Vs + 64 * ATPAD;

    const int qt  = blockIdx.x;
    const int bh  = blockIdx.y;
    const int b   = bh >> 4, h = bh & 15;
    const int tid = threadIdx.x;
    const int lane = tid & 31, w = tid >> 5;
    const int lr = lane >> 2, lc = lane & 3;
    const size_t base = (size_t)(b * S_) * H_ + h * HD_;

    #pragma unroll
    for (int it = 0; it < 4; it++) {
        int slot = tid + it * 128;
        int r = slot >> 3, g = slot & 7;
        const float* src = Q + base + (size_t)(qt * 64 + r) * H_ + g * 8;
        float4 f0 = *(const float4*)src;
        float4 f1 = *(const float4*)(src + 4);
        uint32_t* p = Qs + r * ATPAD + g * 8;
        uint4 u;
        u.x = f2tf(f0.x); u.y = f2tf(f1.x); u.z = f2tf(f0.y); u.w = f2tf(f1.y);
        *(uint4*)p = u;
        u.x = f2tf(f0.z); u.y = f2tf(f1.z); u.z = f2tf(f0.w); u.w = f2tf(f1.w);
        *(uint4*)(p + 4) = u;
    }

    float oacc[8][4];
    #pragma unroll
    for (int i = 0; i < 8; i++)
        #pragma unroll
        for (int j = 0; j < 4; j++) oacc[i][j] = 0.0f;
    float n2lo = 0.0f, n2hi = 0.0f;

    for (int kt = 0; kt <= qt; kt++) {
        __syncthreads();
        #pragma unroll
        for (int it = 0; it < 4; it++) {
            int slot = tid + it * 128;
            int r = slot >> 3, g = slot & 7;
            const float* srck = K + base + (size_t)(kt * 64 + r) * H_ + g * 8;
            float4 f0 = *(const float4*)srck;
            float4 f1 = *(const float4*)(srck + 4);
            uint32_t* p = Ks + r * ATPAD + g * 8;
            uint4 u;
            u.x = f2tf(f0.x); u.y = f2tf(f1.x); u.z = f2tf(f0.y); u.w = f2tf(f1.y);
            *(uint4*)p = u;
            u.x = f2tf(f0.z); u.y = f2tf(f1.z); u.z = f2tf(f0.w); u.w = f2tf(f1.w);
            *(uint4*)(p + 4) = u;
            const float* srcv = V + base + (size_t)(kt * 64 + r) * H_ + g * 8;
            float4 v0 = *(const float4*)srcv;
            float4 v1 = *(const float4*)(srcv + 4);
            uint32_t* pv = Vs + r * ATPAD + g * 8;
            uint4 uv;
            uv.x = f2tf(v0.x); uv.y = f2tf(v0.y); uv.z = f2tf(v0.z); uv.w = f2tf(v0.w);
            *(uint4*)pv = uv;
            uv.x = f2tf(v1.x); uv.y = f2tf(v1.y); uv.z = f2tf(v1.z); uv.w = f2tf(v1.w);
            *(uint4*)(pv + 4) = uv;
        }
        __syncthreads();

        float sacc[8][4];
        #pragma unroll
        for (int i = 0; i < 8; i++)
            #pragma unroll
            for (int j = 0; j < 4; j++) sacc[i][j] = 0.0f;
        #pragma unroll
        for (int ks = 0; ks < 8; ks++) {
            const uint32_t* ap = Qs + (w * 16 + lr) * ATPAD + ks * 8 + lc * 2;
            uint2 p0 = *(const uint2*)ap;
            uint2 p1 = *(const uint2*)(ap + 8 * ATPAD);
            uint32_t a[4] = {p0.x, p1.x, p0.y, p1.y};
            #pragma unroll
            for (int nt = 0; nt < 8; nt++) {
                const uint32_t* bp = Ks + (nt * 8 + lr) * ATPAD + ks * 8 + lc * 2;
                uint2 bb = *(const uint2*)bp;
                uint32_t bfr[2] = {bb.x, bb.y};
                mma_tf32(sacc[nt], a, bfr);
            }
        }

        // mask + gelu + n2 + write Ss (tf32 bits, tf32 pair-interleave: slot=2*(k&3)+((k>>2)&1))
        int q0 = qt * 64 + w * 16 + lr;
        int t7a = 2 * lc, t7b = 2 * lc + 1;
        int oa = 2 * (t7a & 3) + ((t7a >> 2) & 1);
        int ob = 2 * (t7b & 3) + ((t7b >> 2) & 1);
        #pragma unroll
        for (int nt = 0; nt < 8; nt++) {
            int k0c = kt * 64 + nt * 8 + 2 * lc;
            float g0 = (k0c     <= q0)     ? gelu_exact(sacc[nt][0] * 0.125f) : 0.0f;
            float g1 = (k0c + 1 <= q0)     ? gelu_exact(sacc[nt][1] * 0.125f) : 0.0f;
            float g2 = (k0c     <= q0 + 8) ? gelu_exact(sacc[nt][2] * 0.125f) : 0.0f;
            float g3 = (k0c + 1 <= q0 + 8) ? gelu_exact(sacc[nt][3] * 0.125f) : 0.0f;
            n2lo += g0 * g0 + g1 * g1;
            n2hi += g2 * g2 + g3 * g3;
            Ss[(w * 16 + lr)     * ATPAD + nt * 8 + oa] = f2tf(g0);
            Ss[(w * 16 + lr)     * ATPAD + nt * 8 + ob] = f2tf(g1);
            Ss[(w * 16 + lr + 8) * ATPAD + nt * 8 + oa] = f2tf(g2);
            Ss[(w * 16 + lr + 8) * ATPAD + nt * 8 + ob] = f2tf(g3);
        }
        __syncwarp();   // Ss rows are warp-private

        #pragma unroll
        for (int ks = 0; ks < 8; ks++) {
            const uint32_t* ap = Ss + (w * 16 + lr) * ATPAD + ks * 8 + lc * 2;
            uint2 p0 = *(const uint2*)ap;
            uint2 p1 = *(const uint2*)(ap + 8 * ATPAD);
            uint32_t a[4] = {p0.x, p1.x, p0.y, p1.y};
            #pragma unroll
            for (int nt = 0; nt < 8; nt++) {
                uint32_t bfr[2];
                bfr[0] = Vs[(ks * 8 + lc)     * ATPAD + nt * 8 + lr];
                bfr[1] = Vs[(ks * 8 + lc + 4) * ATPAD + nt * 8 + lr];
                mma_tf32(oacc[nt], a, bfr);
            }
        }
    }

    n2lo += __shfl_xor_sync(0xffffffffu, n2lo, 1);
    n2lo += __shfl_xor_sync(0xffffffffu, n2lo, 2);
    n2hi += __shfl_xor_sync(0xffffffffu, n2hi, 1);
    n2hi += __shfl_xor_sync(0xffffffffu, n2hi, 2);

    const float sqS = 45.25483399593904f;
    float sclo = sqS * rsqrtf(n2lo);
    float schi = sqS * rsqrtf(n2hi);

    // store half, k-pair-permuted (feeds proj GEMM as A)
    int r0 = qt * 64 + w * 16 + lr;
    #pragma unroll
    for (int nt = 0; nt < 8; nt++) {
        int c = nt * 8 + 2 * lc;                     // even k index within head
        int pp = (c & ~15) | (2 * hperm((c & 15) >> 1));
        __half* o0 = O + base + (size_t)r0 * H_;
        __half* o1 = O + base + (size_t)(r0 + 8) * H_;
        o0[pp]     = __float2half(oacc[nt][0] * sclo);
        o0[pp + 1] = __float2half(oacc[nt][1] * sclo);
        o1[pp]     = __float2half(oacc[nt][2] * schi);
        o1[pp + 1] = __float2half(oacc[nt][3] * schi);
    }
}

// ---------------- launch ----------------
extern "C" void kernel_launch(void* const* d_in, const int* in_sizes, int n_in,
                              void* d_out, int out_size) {
    const float* x        = (const float*)d_in[0];
    const float* ln1_w    = (const float*)d_in[1];
    const float* ln1_b    = (const float*)d_in[2];
    const float* ln2_w    = (const float*)d_in[3];
    const float* ln2_b    = (const float*)d_in[4];
    const float* q_key    = (const float*)d_in[5];
    const float* q_val    = (const float*)d_in[6];
    const float* k_key    = (const float*)d_in[7];
    const float* k_val    = (const float*)d_in[8];
    const float* v_key    = (const float*)d_in[9];
    const float* v_val    = (const float*)d_in[10];
    const float* proj_key = (const float*)d_in[11];
    const float* proj_val = (const float*)d_in[12];
    const float* ffn_key  = (const float*)d_in[13];
    const float* ffn_val  = (const float*)d_in[14];
    float* out = (float*)d_out;

    float *p_big, *p_q, *p_k, *p_v, *p_x1;
    __half *p_xnh, *p_bigh, *p_oh;
    __half *p_qkh, *p_kkh, *p_vkh, *p_pkh, *p_fkh;
    __half *p_qvh, *p_kvh, *p_vvh, *p_pvh, *p_fvh;
    cudaGetSymbolAddress((void**)&p_big,  d_big);
    cudaGetSymbolAddress((void**)&p_q,    d_q);
    cudaGetSymbolAddress((void**)&p_k,    d_k);
    cudaGetSymbolAddress((void**)&p_v,    d_v);
    cudaGetSymbolAddress((void**)&p_x1,   d_x1);
    cudaGetSymbolAddress((void**)&p_xnh,  d_xnh);
    cudaGetSymbolAddress((void**)&p_bigh, d_bigh);
    cudaGetSymbolAddress((void**)&p_oh,   d_oh);
    cudaGetSymbolAddress((void**)&p_qkh,  d_qkh);
    cudaGetSymbolAddress((void**)&p_kkh,  d_kkh);
    cudaGetSymbolAddress((void**)&p_vkh,  d_vkh);
    cudaGetSymbolAddress((void**)&p_pkh,  d_pkh);
    cudaGetSymbolAddress((void**)&p_fkh,  d_fkh);
    cudaGetSymbolAddress((void**)&p_qvh,  d_qvh);
    cudaGetSymbolAddress((void**)&p_kvh,  d_kvh);
    cudaGetSymbolAddress((void**)&p_vvh,  d_vvh);
    cudaGetSymbolAddress((void**)&p_pvh,  d_pvh);
    cudaGetSymbolAddress((void**)&p_fvh,  d_fvh);

    const float sqrtH = 32.0f;
    dim3 g_small(H_ / 128, T_ / 128);       // (8, 32)
    dim3 g_ffn1(FFN_ / 128, T_ / 128);      // (32, 32)
    dim3 tthr(32, 8);
    dim3 tgrd(H_ / 32, H_ / 32);
    dim3 tgrd_f(H_ / 32, FFN_ / 32);

    const int smem_g = 4 * HTSZ * 8;        // 49152 bytes
    cudaFuncSetAttribute(hgemm_kernel, cudaFuncAttributeMaxDynamicSharedMemorySize, smem_g);

    // preprocess weights -> half permuted
    const int n16_hh = H_ * H_ / 16, n16_fh = FFN_ * H_ / 16;
    round_perm_kernel<<<(n16_hh + 255) / 256, 256>>>(q_key,    p_qkh, n16_hh);
    round_perm_kernel<<<(n16_hh + 255) / 256, 256>>>(k_key,    p_kkh, n16_hh);
    round_perm_kernel<<<(n16_hh + 255) / 256, 256>>>(v_key,    p_vkh, n16_hh);
    round_perm_kernel<<<(n16_hh + 255) / 256, 256>>>(proj_key, p_pkh, n16_hh);
    round_perm_kernel<<<(n16_fh + 255) / 256, 256>>>(ffn_key,  p_fkh, n16_fh);
    transpose_kernel<<<tgrd,   tthr>>>(q_val,    p_qvh, H_,   H_);
    transpose_kernel<<<tgrd,   tthr>>>(k_val,    p_kvh, H_,   H_);
    transpose_kernel<<<tgrd,   tthr>>>(v_val,    p_vvh, H_,   H_);
    transpose_kernel<<<tgrd,   tthr>>>(proj_val, p_pvh, H_,   H_);
    transpose_kernel<<<tgrd_f, tthr>>>(ffn_val,  p_fvh, FFN_, H_);

    ln_kernel<<<T_, 64>>>(x, ln1_w, ln1_b, p_xnh);

    // q / k / v pattention
    hgemm_kernel<<<g_small, 256, smem_g>>>(p_xnh, p_qkh, nullptr, p_big, T_, H_, H_, sqrtH);
    rownorm_kernel<64><<<T_, 64>>>(p_big, p_bigh, H_);
    hgemm_kernel<<<g_small, 256, smem_g>>>(p_bigh, p_qvh, nullptr, p_q, T_, H_, H_, 1.0f);

    hgemm_kernel<<<g_small, 256, smem_g>>>(p_xnh, p_kkh, nullptr, p_big, T_, H_, H_, sqrtH);
    rownorm_kernel<64><<<T_, 64>>>(p_big, p_bigh, H_);
    hgemm_kernel<<<g_small, 256, smem_g>>>(p_bigh, p_kvh, nullptr, p_k, T_, H_, H_, 1.0f);

    hgemm_kernel<<<g_small, 256, smem_g>>>(p_xnh, p_vkh, nullptr, p_big, T_, H_, H_, sqrtH);
    rownorm_kernel<64><<<T_, 64>>>(p_big, p_bigh, H_);
    hgemm_kernel<<<g_small, 256, smem_g>>>(p_bigh, p_vvh, nullptr, p_v, T_, H_, H_, 1.0f);

    rope_kernel<<<(T_ * NH_) / 256, 256>>>(p_q, p_k);

    {
        int smem = 4 * 64 * ATPAD * sizeof(float);
        cudaFuncSetAttribute(attn_kernel, cudaFuncAttributeMaxDynamicSharedMemorySize, smem);
        dim3 grid(S_ / 64, B_ * NH_);
        attn_kernel<<<grid, 128, smem>>>(p_q, p_k, p_v, p_oh);
    }

    // proj pattention + fused residual
    hgemm_kernel<<<g_small, 256, smem_g>>>(p_oh, p_pkh, nullptr, p_big, T_, H_, H_, sqrtH);
    rownorm_kernel<64><<<T_, 64>>>(p_big, p_bigh, H_);
    hgemm_kernel<<<g_small, 256, smem_g>>>(p_bigh, p_pvh, x, p_x1, T_, H_, H_, 1.0f);

    // ffn pattention + fused residual
    ln_kernel<<<T_, 64>>>(p_x1, ln2_w, ln2_b, p_xnh);
    hgemm_kernel<<<g_ffn1, 256, smem_g>>>(p_xnh, p_fkh, nullptr, p_big, T_, FFN_, H_, sqrtH);
    rownorm_kernel<256><<<T_, 256>>>(p_big, p_bigh, FFN_);
    hgemm_kernel<<<g_small, 256, smem_g>>>(p_bigh, p_fvh, p_x1, out, T_, H_, FFN_, 1.0f);
}

// round 9
// speedup vs baseline: 1.3679x; 1.1489x over previous
#include <cuda_runtime.h>
#include <cuda_fp16.h>
#include <math.h>
#include <stdint.h>

// ---------------- problem constants ----------------
#define B_   2
#define S_   2048
#define H_   1024
#define NH_  16
#define HD_  64
#define T_   (B_*S_)      // 4096 tokens
#define FFN_ 4096
#define ROT_ 16

// ---------------- static scratch ----------------
__device__ float  d_big[T_*FFN_];     // gemm1 outputs (fp32, plain)
__device__ float  d_x1 [T_*H_];
__device__ __half d_xnh [T_*H_];      // ln outputs (half, k-permuted)
__device__ __half d_bigh[T_*FFN_];    // rownorm outputs (half, k-permuted)
__device__ __half d_oh  [T_*H_];      // attention output (half, k-permuted)
__device__ __half d_qh  [T_*H_];      // Q (half, k-permuted per 16-dim group)
__device__ __half d_kh  [T_*H_];      // K (half, k-permuted)
__device__ __half d_vh  [T_*H_];      // V (half, plain)
__device__ __half d_vth [T_*H_];      // V^T per head: [b,h,dim,tok] (tok-permuted)
// preprocessed weights (half, k-permuted; vals also transposed)
__device__ __half d_qkh[H_*H_];
__device__ __half d_kkh[H_*H_];
__device__ __half d_vkh[H_*H_];
__device__ __half d_pkh[H_*H_];
__device__ __half d_fkh[FFN_*H_];
__device__ __half d_qvh[H_*H_];
__device__ __half d_kvh[H_*H_];
__device__ __half d_vvh[H_*H_];
__device__ __half d_pvh[H_*H_];
__device__ __half d_fvh[H_*FFN_];

// ---------------- helpers ----------------
__device__ __forceinline__ float gelu_exact(float x) {
    return 0.5f * x * (1.0f + erff(x * 0.7071067811865475f));
}
// half-pair permutation within a 16-k group: pair-unit u (0..7) -> uint slot 2*(u&3)+(u>>2)
__device__ __forceinline__ int hperm(int u) { return 2 * (u & 3) + (u >> 2); }

__device__ __forceinline__ uint32_t h2u(float a, float b) {
    __half2 h = __floats2half2_rn(a, b);
    return *(uint32_t*)&h;
}
__device__ __forceinline__ float2 u2f(uint32_t u) {
    __half2 h = *(__half2*)&u;
    return __half22float2(h);
}
// pack 16 consecutive k-values into permuted half layout (2 uint4)
__device__ __forceinline__ void pack16(const float* f, uint4& lo, uint4& hi) {
    lo.x = h2u(f[0], f[1]);   lo.y = h2u(f[8], f[9]);
    lo.z = h2u(f[2], f[3]);   lo.w = h2u(f[10], f[11]);
    hi.x = h2u(f[4], f[5]);   hi.y = h2u(f[12], f[13]);
    hi.z = h2u(f[6], f[7]);   hi.w = h2u(f[14], f[15]);
}
__device__ __forceinline__ void unpack16(const uint4 lo, const uint4 hi, float* f) {
    float2 t;
    t = u2f(lo.x); f[0]  = t.x; f[1]  = t.y;
    t = u2f(lo.y); f[8]  = t.x; f[9]  = t.y;
    t = u2f(lo.z); f[2]  = t.x; f[3]  = t.y;
    t = u2f(lo.w); f[10] = t.x; f[11] = t.y;
    t = u2f(hi.x); f[4]  = t.x; f[5]  = t.y;
    t = u2f(hi.y); f[12] = t.x; f[13] = t.y;
    t = u2f(hi.z); f[6]  = t.x; f[7]  = t.y;
    t = u2f(hi.w); f[14] = t.x; f[15] = t.y;
}

__device__ __forceinline__ void mma_f16(float* d, const uint32_t* a, const uint32_t* b) {
    asm volatile(
        "mma.sync.aligned.m16n8k16.row.col.f32.f16.f16.f32 "
        "{%0,%1,%2,%3}, {%4,%5,%6,%7}, {%8,%9}, {%0,%1,%2,%3};\n"
        : "+f"(d[0]), "+f"(d[1]), "+f"(d[2]), "+f"(d[3])
        : "r"(a[0]), "r"(a[1]), "r"(a[2]), "r"(a[3]), "r"(b[0]), "r"(b[1]));
}
__device__ __forceinline__ void cp_async16(uint32_t smem_addr, const void* gptr) {
    asm volatile("cp.async.cg.shared.global [%0], [%1], 16;\n" :: "r"(smem_addr), "l"(gptr));
}
#define CP_COMMIT() asm volatile("cp.async.commit_group;\n" ::: "memory")
#define CP_WAIT(n)  asm volatile("cp.async.wait_group %0;\n" :: "n"(n) : "memory")

__device__ __forceinline__ float block_reduce_sum(float v, float* sh) {
    int lane = threadIdx.x & 31, wid = threadIdx.x >> 5;
    #pragma unroll
    for (int o = 16; o > 0; o >>= 1) v += __shfl_down_sync(0xffffffffu, v, o);
    if (lane == 0) sh[wid] = v;
    __syncthreads();
    float r = (threadIdx.x < (blockDim.x >> 5)) ? sh[threadIdx.x] : 0.0f;
    if (wid == 0) {
        #pragma unroll
        for (int o = 4; o > 0; o >>= 1) r += __shfl_down_sync(0xffffffffu, r, o);
        if (lane == 0) sh[0] = r;
    }
    __syncthreads();
    r = sh[0];
    __syncthreads();
    return r;
}

// ---------------- weight prep: fp32 -> half permuted ----------------
__global__ void round_perm_kernel(const float* __restrict__ in, __half* __restrict__ out, int n16) {
    int i = blockIdx.x * blockDim.x + threadIdx.x;
    if (i >= n16) return;
    const float* p = in + (size_t)i * 16;
    float f[16];
    #pragma unroll
    for (int j = 0; j < 16; j += 4) {
        float4 v = *(const float4*)(p + j);
        f[j] = v.x; f[j+1] = v.y; f[j+2] = v.z; f[j+3] = v.w;
    }
    uint4 lo, hi;
    pack16(f, lo, hi);
    uint4* o = (uint4*)(out + (size_t)i * 16);
    o[0] = lo; o[1] = hi;
}

// ---------------- transpose + half + permuted columns (vals) ----------------
__global__ void transpose_kernel(const float* __restrict__ in, __half* __restrict__ out,
                                 int R, int C) {
    __shared__ float t[32][33];
    int x  = blockIdx.x * 32 + threadIdx.x;
    int y0 = blockIdx.y * 32;
    #pragma unroll
    for (int i = threadIdx.y; i < 32; i += 8)
        t[i][threadIdx.x] = in[(size_t)(y0 + i) * C + x];
    __syncthreads();
    int xo = blockIdx.y * 32 + threadIdx.x;        // output column = k index
    int r  = xo & 15;
    int xo_p = (xo & ~15) | (2 * hperm(r >> 1) + (r & 1));
    int yo0 = blockIdx.x * 32;
    #pragma unroll
    for (int i = threadIdx.y; i < 32; i += 8)
        out[(size_t)(yo0 + i) * R + xo_p] = __float2half(t[threadIdx.x][i]);
}

// ---------------- V^T per head: [tok][H] half plain -> [b,h,dim,tok] tok-permuted ----------------
__global__ void vt_kernel(const __half* __restrict__ V, __half* __restrict__ VT) {
    __shared__ __half t[32][34];
    int bh   = blockIdx.z;
    int b    = bh >> 4, h = bh & 15;
    int tok0 = blockIdx.x * 32;
    int dim0 = blockIdx.y * 32;
    int tx = threadIdx.x, ty = threadIdx.y;
    #pragma unroll
    for (int i = ty; i < 32; i += 8)
        t[i][tx] = V[(size_t)(b * S_ + tok0 + i) * H_ + h * HD_ + dim0 + tx];
    __syncthreads();
    int tok = tok0 + tx;
    int tokp = (tok & ~15) | (2 * hperm((tok & 15) >> 1) + (tok & 1));
    #pragma unroll
    for (int i = ty; i < 32; i += 8)
        VT[(size_t)(bh * HD_ + dim0 + i) * S_ + tokp] = t[tx][i];
}

// ---------------- LayerNorm: fp32 in -> half permuted out, 64 threads ----------------
__global__ void ln_kernel(const float* __restrict__ x, const float* __restrict__ w,
                          const float* __restrict__ b, __half* __restrict__ y) {
    __shared__ float sh[32];
    int row = blockIdx.x;
    int tid = threadIdx.x;
    const float* xr = x + (size_t)row * H_ + tid * 16;
    float f[16];
    float s = 0.0f, sq = 0.0f;
    #pragma unroll
    for (int j = 0; j < 16; j += 4) {
        float4 v = *(const float4*)(xr + j);
        f[j] = v.x; f[j+1] = v.y; f[j+2] = v.z; f[j+3] = v.w;
        s  += v.x + v.y + v.z + v.w;
        sq += v.x*v.x + v.y*v.y + v.z*v.z + v.w*v.w;
    }
    float S  = block_reduce_sum(s,  sh);
    float SQ = block_reduce_sum(sq, sh);
    float mu  = S * (1.0f / H_);
    float var = SQ * (1.0f / H_) - mu * mu;
    float inv = rsqrtf(var + 1e-5f);
    const float* wr = w + tid * 16;
    const float* br = b + tid * 16;
    #pragma unroll
    for (int j = 0; j < 16; j++)
        f[j] = (f[j] - mu) * inv * wr[j] + br[j];
    uint4 lo, hi;
    pack16(f, lo, hi);
    uint4* o = (uint4*)(y + (size_t)row * H_ + tid * 16);
    o[0] = lo; o[1] = hi;
}

// ---------------- gelu + L2-rownorm: fp32 in -> half permuted out ----------------
template <int NT>
__global__ void rownorm_kernel(const float* __restrict__ in, __half* __restrict__ out, int cols) {
    __shared__ float sh[32];
    int row = blockIdx.x;
    int tid = threadIdx.x;
    const float* ar = in + (size_t)row * cols + tid * 16;
    float g[16];
    float s = 0.0f;
    #pragma unroll
    for (int j = 0; j < 16; j += 4) {
        float4 v = *(const float4*)(ar + j);
        g[j]   = gelu_exact(v.x); g[j+1] = gelu_exact(v.y);
        g[j+2] = gelu_exact(v.z); g[j+3] = gelu_exact(v.w);
        s += g[j]*g[j] + g[j+1]*g[j+1] + g[j+2]*g[j+2] + g[j+3]*g[j+3];
    }
    float tot = block_reduce_sum(s, sh);
    float sc = sqrtf((float)cols) * rsqrtf(tot);
    #pragma unroll
    for (int j = 0; j < 16; j++) g[j] *= sc;
    uint4 lo, hi;
    pack16(g, lo, hi);
    uint4* o = (uint4*)(out + (size_t)row * cols + tid * 16);
    o[0] = lo; o[1] = hi;
}

// ---------------- FP16 tensor-core GEMM, NT, 128x128x32, cp.async 2-stage ----------------
// C = alpha * A[M,K] @ B[N,K]^T (+ Res in mode 0).  A,B half, k-pair-permuted.
// EMODE: 0 = fp32 plain (+res), 1 = half k-permuted, 2 = half plain.
#define HSTR 12
#define HTSZ (128 * HSTR)

template <int EMODE>
__global__ void __launch_bounds__(256) hgemm_kernel(
    const __half* __restrict__ A, const __half* __restrict__ Bm,
    const float* __restrict__ Res, void* __restrict__ Cv,
    int M, int N, int K, float alpha)
{
    extern __shared__ uint2 sh2[];
    uint2* As = sh2;              // [2][HTSZ]
    uint2* Bs = sh2 + 2 * HTSZ;   // [2][HTSZ]

    const int bx = blockIdx.x, by = blockIdx.y;
    const int tid = threadIdx.x;
    const int lane = tid & 31, w = tid >> 5;
    const int wm = w & 3, wn = w >> 2;          // 4x2 warps; warp tile 32m x 64n
    const int lr = lane >> 2, lc = lane & 3;

    float acc[2][8][4];
    #pragma unroll
    for (int i = 0; i < 2; i++)
        #pragma unroll
        for (int j = 0; j < 8; j++)
            #pragma unroll
            for (int t = 0; t < 4; t++) acc[i][j][t] = 0.0f;

    const int iters = K >> 5;
    const int r_ld = tid >> 1;          // 0..127
    const int c2   = (tid & 1) * 2;     // chunk 0/2

    auto load_tile = [&](int t, int buf) {
        int k0 = t << 5;
        const __half* srcA = A + (size_t)(by * 128 + r_ld) * K + k0 + c2 * 8;
        uint32_t dA = (uint32_t)__cvta_generic_to_shared(As + buf * HTSZ + r_ld * HSTR + c2 * 2);
        cp_async16(dA,      srcA);
        cp_async16(dA + 16, srcA + 8);
        const __half* srcB = Bm + (size_t)(bx * 128 + r_ld) * K + k0 + c2 * 8;
        uint32_t dB = (uint32_t)__cvta_generic_to_shared(Bs + buf * HTSZ + r_ld * HSTR + c2 * 2);
        cp_async16(dB,      srcB);
        cp_async16(dB + 16, srcB + 8);
    };

    load_tile(0, 0);
    CP_COMMIT();

    int buf = 0;
    for (int t = 0; t < iters; t++) {
        if (t + 1 < iters) {
            load_tile(t + 1, buf ^ 1);
            CP_COMMIT();
            CP_WAIT(1);
        } else {
            CP_WAIT(0);
        }
        __syncthreads();

        const uint2* Ab = As + buf * HTSZ;
        const uint2* Bb = Bs + buf * HTSZ;
        #pragma unroll
        for (int ks = 0; ks < 2; ks++) {
            uint32_t afr[2][4];
            #pragma unroll
            for (int mt = 0; mt < 2; mt++) {
                const uint2* ap = Ab + (wm * 32 + mt * 16 + lr) * HSTR + ks * 4 + lc;
                uint2 p0 = ap[0];
                uint2 p1 = ap[8 * HSTR];
                afr[mt][0] = p0.x; afr[mt][1] = p1.x;
                afr[mt][2] = p0.y; afr[mt][3] = p1.y;
            }
            #pragma unroll
            for (int nt = 0; nt < 8; nt++) {
                const uint2* bp = Bb + (wn * 64 + nt * 8 + lr) * HSTR + ks * 4 + lc;
                uint2 bb = bp[0];
                uint32_t bfr[2] = {bb.x, bb.y};
                mma_f16(acc[0][nt], afr[0], bfr);
                mma_f16(acc[1][nt], afr[1], bfr);
            }
        }
        buf ^= 1;
        __syncthreads();
    }

    // epilogue
    #pragma unroll
    for (int mt = 0; mt < 2; mt++) {
        int r0 = by * 128 + wm * 32 + mt * 16 + lr;
        #pragma unroll
        for (int nt = 0; nt < 8; nt++) {
            int c = bx * 128 + wn * 64 + nt * 8 + 2 * lc;
            float a0 = acc[mt][nt][0] * alpha, a1 = acc[mt][nt][1] * alpha;
            float a2 = acc[mt][nt][2] * alpha, a3 = acc[mt][nt][3] * alpha;
            if (EMODE == 0) {
                float* C = (float*)Cv;
                float2 lo = {a0, a1}, hi = {a2, a3};
                if (Res) {
                    float2 rlo = *(const float2*)(Res + (size_t)r0 * N + c);
                    float2 rhi = *(const float2*)(Res + (size_t)(r0 + 8) * N + c);
                    lo.x += rlo.x; lo.y += rlo.y; hi.x += rhi.x; hi.y += rhi.y;
                }
                *(float2*)(C + (size_t)r0 * N + c)       = lo;
                *(float2*)(C + (size_t)(r0 + 8) * N + c) = hi;
            } else if (EMODE == 1) {
                __half* C = (__half*)Cv;
                int hoff = (c & ~15) + 4 * lc + 2 * (nt & 1);   // permuted pair slot
                ((uint32_t*)(C + (size_t)r0 * N))[hoff >> 1]       = h2u(a0, a1);
                ((uint32_t*)(C + (size_t)(r0 + 8) * N))[hoff >> 1] = h2u(a2, a3);
            } else {
                __half* C = (__half*)Cv;
                ((uint32_t*)(C + (size_t)r0 * N))[c >> 1]       = h2u(a0, a1);
                ((uint32_t*)(C + (size_t)(r0 + 8) * N))[c >> 1] = h2u(a2, a3);
            }
        }
    }
}

// ---------------- RoPE on half k-permuted Q,K (rotates dims 0..15 = group 0 of each head) --------
__global__ void rope_kernel(__half* __restrict__ q, __half* __restrict__ k) {
    int idx = blockIdx.x * blockDim.x + threadIdx.x;
    if (idx >= T_ * NH_) return;
    int h  = idx & (NH_ - 1);
    int bs = idx >> 4;
    int s  = bs & (S_ - 1);
    __half* qp = q + (size_t)bs * H_ + h * HD_;
    __half* kp = k + (size_t)bs * H_ + h * HD_;
    uint4 qlo = *(uint4*)qp, qhi = *(uint4*)(qp + 8);
    uint4 klo = *(uint4*)kp, khi = *(uint4*)(kp + 8);
    float qv[16], kv[16];
    unpack16(qlo, qhi, qv);
    unpack16(klo, khi, kv);
    #pragma unroll
    for (int i = 0; i < ROT_ / 2; i++) {
        double invf = pow(10000.0, -(double)(2 * i) / (double)ROT_);
        double ang = (double)s * invf;
        float c  = (float)cos(ang);
        float sn = (float)sin(ang);
        float q0 = qv[i], q1 = qv[i + 8];
        qv[i]     = q0 * c - q1 * sn;
        qv[i + 8] = q1 * c + q0 * sn;
        float k0 = kv[i], k1 = kv[i + 8];
        kv[i]     = k0 * c - k1 * sn;
        kv[i + 8] = k1 * c + k0 * sn;
    }
    pack16(qv, qlo, qhi);
    pack16(kv, klo, khi);
    *(uint4*)qp = qlo; *(uint4*)(qp + 8) = qhi;
    *(uint4*)kp = klo; *(uint4*)(kp + 8) = khi;
}

// ---------------- fused causal attention (fp16 mma, single pass, cp.async dbl-buffered K/V) ------
// O = (sum gelu(qk/8)*V) * sqrt(S)/sqrt(sum gelu^2). masked entries exactly 0.
// Q,K: [tok][H] half k-permuted; VT: [b,h,dim,S] half tok-permuted; O: half k-permuted.
#define VSTR 20               // uint2 per smem row (16 uint2 data + 4 pad)
#define ATSZ (64 * VSTR)      // uint2 per tile

__global__ void __launch_bounds__(128, 2) attn_kernel(
    const __half* __restrict__ Q, const __half* __restrict__ K,
    const __half* __restrict__ VT, __half* __restrict__ O)
{
    extern __shared__ uint2 sm2[];
    uint2* Qs = sm2;                 // [64][VSTR]
    uint2* Ks = Qs + ATSZ;           // [2][64][VSTR]
    uint2* Vs = Ks + 2 * ATSZ;       // [2][64][VSTR]
    uint2* Ss = Vs + 2 * ATSZ;       // [64][VSTR]

    const int qt  = blockIdx.x;
    const int bh  = blockIdx.y;
    const int b   = bh >> 4, h = bh & 15;
    const int tid = threadIdx.x;
    const int lane = tid & 31, w = tid >> 5;
    const int lr = lane >> 2, lc = lane & 3;
    const size_t baseQK = (size_t)(b * S_) * H_ + h * HD_;
    const size_t baseVT = (size_t)(bh * HD_) * S_;

    // fill Q tile: 64 rows x 8 chunks of 16B (chunk off -> uint2 slot off*2)
    #pragma unroll
    for (int it = 0; it < 4; it++) {
        int c = tid + it * 128;
        int r = c >> 3, off = c & 7;
        const __half* src = Q + baseQK + (size_t)(qt * 64 + r) * H_ + off * 8;
        uint32_t dst = (uint32_t)__cvta_generic_to_shared(Qs + r * VSTR + off * 2);
        cp_async16(dst, src);
    }
    // fill K/V tile kt=0 into buf 0
    #pragma unroll
    for (int it = 0; it < 4; it++) {
        int c = tid + it * 128;
        int r = c >> 3, off = c & 7;
        const __half* srck = K + baseQK + (size_t)(r) * H_ + off * 8;
        uint32_t dk = (uint32_t)__cvta_generic_to_shared(Ks + r * VSTR + off * 2);
        cp_async16(dk, srck);
        const __half* srcv = VT + baseVT + (size_t)r * S_ + off * 8;
        uint32_t dv = (uint32_t)__cvta_generic_to_shared(Vs + r * VSTR + off * 2);
        cp_async16(dv, srcv);
    }
    CP_COMMIT();

    float oacc[8][4];
    #pragma unroll
    for (int i = 0; i < 8; i++)
        #pragma unroll
        for (int j = 0; j < 4; j++) oacc[i][j] = 0.0f;
    float n2lo = 0.0f, n2hi = 0.0f;

    int buf = 0;
    for (int kt = 0; kt <= qt; kt++) {
        CP_WAIT(0);
        __syncthreads();   // data visible; all warps done with buf^1 from prev iter

        if (kt < qt) {
            #pragma unroll
            for (int it = 0; it < 4; it++) {
                int c = tid + it * 128;
                int r = c >> 3, off = c & 7;
                const __half* srck = K + baseQK + (size_t)((kt + 1) * 64 + r) * H_ + off * 8;
                uint32_t dk = (uint32_t)__cvta_generic_to_shared(Ks + (buf ^ 1) * ATSZ + r * VSTR + off * 2);
                cp_async16(dk, srck);
                const __half* srcv = VT + baseVT + (size_t)r * S_ + (kt + 1) * 64 + off * 8;
                uint32_t dv = (uint32_t)__cvta_generic_to_shared(Vs + (buf ^ 1) * ATSZ + r * VSTR + off * 2);
                cp_async16(dv, srcv);
            }
            CP_COMMIT();
        }

        const uint2* Kb = Ks + buf * ATSZ;
        const uint2* Vb = Vs + buf * ATSZ;

        // S = Q K^T (fp16 mma): per warp 16q x 64tok, 4 k16 steps
        float sacc[8][4];
        #pragma unroll
        for (int i = 0; i < 8; i++)
            #pragma unroll
            for (int j = 0; j < 4; j++) sacc[i][j] = 0.0f;
        #pragma unroll
        for (int ks = 0; ks < 4; ks++) {
            const uint2* ap = Qs + (w * 16 + lr) * VSTR + ks * 4 + lc;
            uint2 p0 = ap[0];
            uint2 p1 = ap[8 * VSTR];
            uint32_t a[4] = {p0.x, p1.x, p0.y, p1.y};
            #pragma unroll
            for (int nt = 0; nt < 8; nt++) {
                uint2 bb = Kb[(nt * 8 + lr) * VSTR + ks * 4 + lc];
                uint32_t bfr[2] = {bb.x, bb.y};
                mma_f16(sacc[nt], a, bfr);
            }
        }

        // mask + gelu + n2 + pack to Ss (half pairs, tok-permuted)
        int q0 = qt * 64 + w * 16 + lr;
        uint32_t* Ss32 = (uint32_t*)Ss;
        #pragma unroll
        for (int nt = 0; nt < 8; nt++) {
            int k0c = kt * 64 + nt * 8 + 2 * lc;
            float g0 = (k0c     <= q0)     ? gelu_exact(sacc[nt][0] * 0.125f) : 0.0f;
            float g1 = (k0c + 1 <= q0)     ? gelu_exact(sacc[nt][1] * 0.125f) : 0.0f;
            float g2 = (k0c     <= q0 + 8) ? gelu_exact(sacc[nt][2] * 0.125f) : 0.0f;
            float g3 = (k0c + 1 <= q0 + 8) ? gelu_exact(sacc[nt][3] * 0.125f) : 0.0f;
            n2lo += g0 * g0 + g1 * g1;
            n2hi += g2 * g2 + g3 * g3;
            int slot = (nt >> 1) * 8 + 2 * lc + (nt & 1);       // permuted uint slot
            Ss32[(w * 16 + lr)     * (2 * VSTR) + slot] = h2u(g0, g1);
            Ss32[(w * 16 + lr + 8) * (2 * VSTR) + slot] = h2u(g2, g3);
        }
        __syncwarp();   // Ss rows are warp-private

        // O += Ss @ V (fp16 mma): 4 k16 steps over 64 toks
        #pragma unroll
        for (int ks = 0; ks < 4; ks++) {
            const uint2* ap = Ss + (w * 16 + lr) * VSTR + ks * 4 + lc;
            uint2 p0 = ap[0];
            uint2 p1 = ap[8 * VSTR];
            uint32_t a[4] = {p0.x, p1.x, p0.y, p1.y};
            #pragma unroll
            for (int nt = 0; nt < 8; nt++) {
                uint2 bb = Vb[(nt * 8 + lr) * VSTR + ks * 4 + lc];
                uint32_t bfr[2] = {bb.x, bb.y};
                mma_f16(oacc[nt], a, bfr);
            }
        }
        buf ^= 1;
    }

    n2lo += __shfl_xor_sync(0xffffffffu, n2lo, 1);
    n2lo += __shfl_xor_sync(0xffffffffu, n2lo, 2);
    n2hi += __shfl_xor_sync(0xffffffffu, n2hi, 1);
    n2hi += __shfl_xor_sync(0xffffffffu, n2hi, 2);

    const float sqS = 45.25483399593904f;
    float sclo = sqS * rsqrtf(n2lo);
    float schi = sqS * rsqrtf(n2hi);

    // store half, k-pair-permuted (feeds proj GEMM as A)
    int r0 = qt * 64 + w * 16 + lr;
    #pragma unroll
    for (int nt = 0; nt < 8; nt++) {
        int c = nt * 8 + 2 * lc;                     // even dim index within head
        int pp = (c & ~15) | (2 * hperm((c & 15) >> 1));
        __half* o0 = O + baseQK + (size_t)r0 * H_;
        __half* o1 = O + baseQK + (size_t)(r0 + 8) * H_;
        ((uint32_t*)o0)[pp >> 1] = h2u(oacc[nt][0] * sclo, oacc[nt][1] * sclo);
        ((uint32_t*)o1)[pp >> 1] = h2u(oacc[nt][2] * schi, oacc[nt][3] * schi);
    }
}

// ---------------- launch ----------------
extern "C" void kernel_launch(void* const* d_in, const int* in_sizes, int n_in,
                              void* d_out, int out_size) {
    const float* x        = (const float*)d_in[0];
    const float* ln1_w    = (const float*)d_in[1];
    const float* ln1_b    = (const float*)d_in[2];
    const float* ln2_w    = (const float*)d_in[3];
    const float* ln2_b    = (const float*)d_in[4];
    const float* q_key    = (const float*)d_in[5];
    const float* q_val    = (const float*)d_in[6];
    const float* k_key    = (const float*)d_in[7];
    const float* k_val    = (const float*)d_in[8];
    const float* v_key    = (const float*)d_in[9];
    const float* v_val    = (const float*)d_in[10];
    const float* proj_key = (const float*)d_in[11];
    const float* proj_val = (const float*)d_in[12];
    const float* ffn_key  = (const float*)d_in[13];
    const float* ffn_val  = (const float*)d_in[14];
    float* out = (float*)d_out;

    float *p_big, *p_x1;
    __half *p_xnh, *p_bigh, *p_oh, *p_qh, *p_kh, *p_vh, *p_vth;
    __half *p_qkh, *p_kkh, *p_vkh, *p_pkh, *p_fkh;
    __half *p_qvh, *p_kvh, *p_vvh, *p_pvh, *p_fvh;
    cudaGetSymbolAddress((void**)&p_big,  d_big);
    cudaGetSymbolAddress((void**)&p_x1,   d_x1);
    cudaGetSymbolAddress((void**)&p_xnh,  d_xnh);
    cudaGetSymbolAddress((void**)&p_bigh, d_bigh);
    cudaGetSymbolAddress((void**)&p_oh,   d_oh);
    cudaGetSymbolAddress((void**)&p_qh,   d_qh);
    cudaGetSymbolAddress((void**)&p_kh,   d_kh);
    cudaGetSymbolAddress((void**)&p_vh,   d_vh);
    cudaGetSymbolAddress((void**)&p_vth,  d_vth);
    cudaGetSymbolAddress((void**)&p_qkh,  d_qkh);
    cudaGetSymbolAddress((void**)&p_kkh,  d_kkh);
    cudaGetSymbolAddress((void**)&p_vkh,  d_vkh);
    cudaGetSymbolAddress((void**)&p_pkh,  d_pkh);
    cudaGetSymbolAddress((void**)&p_fkh,  d_fkh);
    cudaGetSymbolAddress((void**)&p_qvh,  d_qvh);
    cudaGetSymbolAddress((void**)&p_kvh,  d_kvh);
    cudaGetSymbolAddress((void**)&p_vvh,  d_vvh);
    cudaGetSymbolAddress((void**)&p_pvh,  d_pvh);
    cudaGetSymbolAddress((void**)&p_fvh,  d_fvh);

    const float sqrtH = 32.0f;
    dim3 g_small(H_ / 128, T_ / 128);       // (8, 32)
    dim3 g_ffn1(FFN_ / 128, T_ / 128);      // (32, 32)
    dim3 tthr(32, 8);
    dim3 tgrd(H_ / 32, H_ / 32);
    dim3 tgrd_f(H_ / 32, FFN_ / 32);

    const int smem_g = 4 * HTSZ * 8;        // 49152 bytes
    cudaFuncSetAttribute(hgemm_kernel<0>, cudaFuncAttributeMaxDynamicSharedMemorySize, smem_g);
    cudaFuncSetAttribute(hgemm_kernel<1>, cudaFuncAttributeMaxDynamicSharedMemorySize, smem_g);
    cudaFuncSetAttribute(hgemm_kernel<2>, cudaFuncAttributeMaxDynamicSharedMemorySize, smem_g);

    // preprocess weights -> half permuted
    const int n16_hh = H_ * H_ / 16, n16_fh = FFN_ * H_ / 16;
    round_perm_kernel<<<(n16_hh + 255) / 256, 256>>>(q_key,    p_qkh, n16_hh);
    round_perm_kernel<<<(n16_hh + 255) / 256, 256>>>(k_key,    p_kkh, n16_hh);
    round_perm_kernel<<<(n16_hh + 255) / 256, 256>>>(v_key,    p_vkh, n16_hh);
    round_perm_kernel<<<(n16_hh + 255) / 256, 256>>>(proj_key, p_pkh, n16_hh);
    round_perm_kernel<<<(n16_fh + 255) / 256, 256>>>(ffn_key,  p_fkh, n16_fh);
    transpose_kernel<<<tgrd,   tthr>>>(q_val,    p_qvh, H_,   H_);
    transpose_kernel<<<tgrd,   tthr>>>(k_val,    p_kvh, H_,   H_);
    transpose_kernel<<<tgrd,   tthr>>>(v_val,    p_vvh, H_,   H_);
    transpose_kernel<<<tgrd,   tthr>>>(proj_val, p_pvh, H_,   H_);
    transpose_kernel<<<tgrd_f, tthr>>>(ffn_val,  p_fvh, FFN_, H_);

    ln_kernel<<<T_, 64>>>(x, ln1_w, ln1_b, p_xnh);

    // q / k / v pattention (Q,K emitted half-perm; V half-plain)
    hgemm_kernel<0><<<g_small, 256, smem_g>>>(p_xnh, p_qkh, nullptr, p_big, T_, H_, H_, sqrtH);
    rownorm_kernel<64><<<T_, 64>>>(p_big, p_bigh, H_);
    hgemm_kernel<1><<<g_small, 256, smem_g>>>(p_bigh, p_qvh, nullptr, p_qh, T_, H_, H_, 1.0f);

    hgemm_kernel<0><<<g_small, 256, smem_g>>>(p_xnh, p_kkh, nullptr, p_big, T_, H_, H_, sqrtH);
    rownorm_kernel<64><<<T_, 64>>>(p_big, p_bigh, H_);
    hgemm_kernel<1><<<g_small, 256, smem_g>>>(p_bigh, p_kvh, nullptr, p_kh, T_, H_, H_, 1.0f);

    hgemm_kernel<0><<<g_small, 256, smem_g>>>(p_xnh, p_vkh, nullptr, p_big, T_, H_, H_, sqrtH);
    rownorm_kernel<64><<<T_, 64>>>(p_big, p_bigh, H_);
    hgemm_kernel<2><<<g_small, 256, smem_g>>>(p_bigh, p_vvh, nullptr, p_vh, T_, H_, H_, 1.0f);

    rope_kernel<<<(T_ * NH_) / 256, 256>>>(p_qh, p_kh);

    {
        dim3 vtg(S_ / 32, HD_ / 32, B_ * NH_);
        vt_kernel<<<vtg, tthr>>>(p_vh, p_vth);
    }

    {
        int smem = 6 * ATSZ * 8;    // 61440 bytes
        cudaFuncSetAttribute(attn_kernel, cudaFuncAttributeMaxDynamicSharedMemorySize, smem);
        dim3 grid(S_ / 64, B_ * NH_);
        attn_kernel<<<grid, 128, smem>>>(p_qh, p_kh, p_vth, p_oh);
    }

    // proj pattention + fused residual
    hgemm_kernel<0><<<g_small, 256, smem_g>>>(p_oh, p_pkh, nullptr, p_big, T_, H_, H_, sqrtH);
    rownorm_kernel<64><<<T_, 64>>>(p_big, p_bigh, H_);
    hgemm_kernel<0><<<g_small, 256, smem_g>>>(p_bigh, p_pvh, x, p_x1, T_, H_, H_, 1.0f);

    // ffn pattention + fused residual
    ln_kernel<<<T_, 64>>>(p_x1, ln2_w, ln2_b, p_xnh);
    hgemm_kernel<0><<<g_ffn1, 256, smem_g>>>(p_xnh, p_fkh, nullptr, p_big, T_, FFN_, H_, sqrtH);
    rownorm_kernel<256><<<T_, 256>>>(p_big, p_bigh, FFN_);
    hgemm_kernel<0><<<g_small, 256, smem_g>>>(p_bigh, p_fvh, p_x1, out, T_, H_, FFN_, 1.0f);
}

// round 10
// speedup vs baseline: 1.3822x; 1.0104x over previous
#include <cuda_runtime.h>
#include <cuda_fp16.h>
#include <math.h>
#include <stdint.h>

// ---------------- problem constants ----------------
#define B_   2
#define S_   2048
#define H_   1024
#define NH_  16
#define HD_  64
#define T_   (B_*S_)      // 4096 tokens
#define FFN_ 4096
#define ROT_ 16

// ---------------- static scratch ----------------
__device__ float  d_big[T_*FFN_];     // gemm1 outputs (fp32, plain)
__device__ float  d_x1 [T_*H_];
__device__ __half d_xnh [T_*H_];      // ln outputs (half, k-permuted)
__device__ __half d_bigh[T_*FFN_];    // rownorm outputs (half, k-permuted)
__device__ __half d_oh  [T_*H_];      // attention output (half, k-permuted)
__device__ __half d_qh  [T_*H_];      // Q (half, k-permuted per 16-dim group)
__device__ __half d_kh  [T_*H_];      // K (half, k-permuted)
__device__ __half d_vh  [T_*H_];      // V (half, plain)
__device__ __half d_vth [T_*H_];      // V^T per head: [b,h,dim,tok] (tok-permuted)
// preprocessed weights (half, k-permuted; vals also transposed)
__device__ __half d_qkh[H_*H_];
__device__ __half d_kkh[H_*H_];
__device__ __half d_vkh[H_*H_];
__device__ __half d_pkh[H_*H_];
__device__ __half d_fkh[FFN_*H_];
__device__ __half d_qvh[H_*H_];
__device__ __half d_kvh[H_*H_];
__device__ __half d_vvh[H_*H_];
__device__ __half d_pvh[H_*H_];
__device__ __half d_fvh[H_*FFN_];

// ---------------- helpers ----------------
__device__ __forceinline__ float gelu_exact(float x) {
    return 0.5f * x * (1.0f + erff(x * 0.7071067811865475f));
}
// half-pair permutation within a 16-k group: pair-unit u (0..7) -> uint slot 2*(u&3)+(u>>2)
__device__ __forceinline__ int hperm(int u) { return 2 * (u & 3) + (u >> 2); }

__device__ __forceinline__ uint32_t h2u(float a, float b) {
    __half2 h = __floats2half2_rn(a, b);
    return *(uint32_t*)&h;
}
__device__ __forceinline__ float2 u2f(uint32_t u) {
    __half2 h = *(__half2*)&u;
    return __half22float2(h);
}
// pack 16 consecutive k-values into permuted half layout (2 uint4)
__device__ __forceinline__ void pack16(const float* f, uint4& lo, uint4& hi) {
    lo.x = h2u(f[0], f[1]);   lo.y = h2u(f[8], f[9]);
    lo.z = h2u(f[2], f[3]);   lo.w = h2u(f[10], f[11]);
    hi.x = h2u(f[4], f[5]);   hi.y = h2u(f[12], f[13]);
    hi.z = h2u(f[6], f[7]);   hi.w = h2u(f[14], f[15]);
}
__device__ __forceinline__ void unpack16(const uint4 lo, const uint4 hi, float* f) {
    float2 t;
    t = u2f(lo.x); f[0]  = t.x; f[1]  = t.y;
    t = u2f(lo.y); f[8]  = t.x; f[9]  = t.y;
    t = u2f(lo.z); f[2]  = t.x; f[3]  = t.y;
    t = u2f(lo.w); f[10] = t.x; f[11] = t.y;
    t = u2f(hi.x); f[4]  = t.x; f[5]  = t.y;
    t = u2f(hi.y); f[12] = t.x; f[13] = t.y;
    t = u2f(hi.z); f[6]  = t.x; f[7]  = t.y;
    t = u2f(hi.w); f[14] = t.x; f[15] = t.y;
}

__device__ __forceinline__ void mma_f16(float* d, const uint32_t* a, const uint32_t* b) {
    asm volatile(
        "mma.sync.aligned.m16n8k16.row.col.f32.f16.f16.f32 "
        "{%0,%1,%2,%3}, {%4,%5,%6,%7}, {%8,%9}, {%0,%1,%2,%3};\n"
        : "+f"(d[0]), "+f"(d[1]), "+f"(d[2]), "+f"(d[3])
        : "r"(a[0]), "r"(a[1]), "r"(a[2]), "r"(a[3]), "r"(b[0]), "r"(b[1]));
}
__device__ __forceinline__ void cp_async16(uint32_t smem_addr, const void* gptr) {
    asm volatile("cp.async.cg.shared.global [%0], [%1], 16;\n" :: "r"(smem_addr), "l"(gptr));
}
#define CP_COMMIT() asm volatile("cp.async.commit_group;\n" ::: "memory")
#define CP_WAIT(n)  asm volatile("cp.async.wait_group %0;\n" :: "n"(n) : "memory")

__device__ __forceinline__ float block_reduce_sum(float v, float* sh) {
    int lane = threadIdx.x & 31, wid = threadIdx.x >> 5;
    #pragma unroll
    for (int o = 16; o > 0; o >>= 1) v += __shfl_down_sync(0xffffffffu, v, o);
    if (lane == 0) sh[wid] = v;
    __syncthreads();
    float r = (threadIdx.x < (blockDim.x >> 5)) ? sh[threadIdx.x] : 0.0f;
    if (wid == 0) {
        #pragma unroll
        for (int o = 4; o > 0; o >>= 1) r += __shfl_down_sync(0xffffffffu, r, o);
        if (lane == 0) sh[0] = r;
    }
    __syncthreads();
    r = sh[0];
    __syncthreads();
    return r;
}

// ---------------- weight prep: fp32 -> half permuted ----------------
__global__ void round_perm_kernel(const float* __restrict__ in, __half* __restrict__ out, int n16) {
    int i = blockIdx.x * blockDim.x + threadIdx.x;
    if (i >= n16) return;
    const float* p = in + (size_t)i * 16;
    float f[16];
    #pragma unroll
    for (int j = 0; j < 16; j += 4) {
        float4 v = *(const float4*)(p + j);
        f[j] = v.x; f[j+1] = v.y; f[j+2] = v.z; f[j+3] = v.w;
    }
    uint4 lo, hi;
    pack16(f, lo, hi);
    uint4* o = (uint4*)(out + (size_t)i * 16);
    o[0] = lo; o[1] = hi;
}

// ---------------- transpose + half + permuted columns (vals) ----------------
__global__ void transpose_kernel(const float* __restrict__ in, __half* __restrict__ out,
                                 int R, int C) {
    __shared__ float t[32][33];
    int x  = blockIdx.x * 32 + threadIdx.x;
    int y0 = blockIdx.y * 32;
    #pragma unroll
    for (int i = threadIdx.y; i < 32; i += 8)
        t[i][threadIdx.x] = in[(size_t)(y0 + i) * C + x];
    __syncthreads();
    int xo = blockIdx.y * 32 + threadIdx.x;        // output column = k index
    int r  = xo & 15;
    int xo_p = (xo & ~15) | (2 * hperm(r >> 1) + (r & 1));
    int yo0 = blockIdx.x * 32;
    #pragma unroll
    for (int i = threadIdx.y; i < 32; i += 8)
        out[(size_t)(yo0 + i) * R + xo_p] = __float2half(t[threadIdx.x][i]);
}

// ---------------- V^T per head: [tok][H] half plain -> [b,h,dim,tok] tok-permuted ----------------
__global__ void vt_kernel(const __half* __restrict__ V, __half* __restrict__ VT) {
    __shared__ __half t[32][34];
    int bh   = blockIdx.z;
    int b    = bh >> 4, h = bh & 15;
    int tok0 = blockIdx.x * 32;
    int dim0 = blockIdx.y * 32;
    int tx = threadIdx.x, ty = threadIdx.y;
    #pragma unroll
    for (int i = ty; i < 32; i += 8)
        t[i][tx] = V[(size_t)(b * S_ + tok0 + i) * H_ + h * HD_ + dim0 + tx];
    __syncthreads();
    int tok = tok0 + tx;
    int tokp = (tok & ~15) | (2 * hperm((tok & 15) >> 1) + (tok & 1));
    #pragma unroll
    for (int i = ty; i < 32; i += 8)
        VT[(size_t)(bh * HD_ + dim0 + i) * S_ + tokp] = t[tx][i];
}

// ---------------- LayerNorm: fp32 in -> half permuted out, 64 threads ----------------
__global__ void ln_kernel(const float* __restrict__ x, const float* __restrict__ w,
                          const float* __restrict__ b, __half* __restrict__ y) {
    __shared__ float sh[32];
    int row = blockIdx.x;
    int tid = threadIdx.x;
    const float* xr = x + (size_t)row * H_ + tid * 16;
    float f[16];
    float s = 0.0f, sq = 0.0f;
    #pragma unroll
    for (int j = 0; j < 16; j += 4) {
        float4 v = *(const float4*)(xr + j);
        f[j] = v.x; f[j+1] = v.y; f[j+2] = v.z; f[j+3] = v.w;
        s  += v.x + v.y + v.z + v.w;
        sq += v.x*v.x + v.y*v.y + v.z*v.z + v.w*v.w;
    }
    float S  = block_reduce_sum(s,  sh);
    float SQ = block_reduce_sum(sq, sh);
    float mu  = S * (1.0f / H_);
    float var = SQ * (1.0f / H_) - mu * mu;
    float inv = rsqrtf(var + 1e-5f);
    const float* wr = w + tid * 16;
    const float* br = b + tid * 16;
    #pragma unroll
    for (int j = 0; j < 16; j++)
        f[j] = (f[j] - mu) * inv * wr[j] + br[j];
    uint4 lo, hi;
    pack16(f, lo, hi);
    uint4* o = (uint4*)(y + (size_t)row * H_ + tid * 16);
    o[0] = lo; o[1] = hi;
}

// ---------------- gelu + L2-rownorm: fp32 in -> half permuted out ----------------
template <int NT>
__global__ void rownorm_kernel(const float* __restrict__ in, __half* __restrict__ out, int cols) {
    __shared__ float sh[32];
    int row = blockIdx.x;
    int tid = threadIdx.x;
    const float* ar = in + (size_t)row * cols + tid * 16;
    float g[16];
    float s = 0.0f;
    #pragma unroll
    for (int j = 0; j < 16; j += 4) {
        float4 v = *(const float4*)(ar + j);
        g[j]   = gelu_exact(v.x); g[j+1] = gelu_exact(v.y);
        g[j+2] = gelu_exact(v.z); g[j+3] = gelu_exact(v.w);
        s += g[j]*g[j] + g[j+1]*g[j+1] + g[j+2]*g[j+2] + g[j+3]*g[j+3];
    }
    float tot = block_reduce_sum(s, sh);
    float sc = sqrtf((float)cols) * rsqrtf(tot);
    #pragma unroll
    for (int j = 0; j < 16; j++) g[j] *= sc;
    uint4 lo, hi;
    pack16(g, lo, hi);
    uint4* o = (uint4*)(out + (size_t)row * cols + tid * 16);
    o[0] = lo; o[1] = hi;
}

// ---------------- FP16 tensor-core GEMM, NT, 128x128x32, cp.async 2-stage, 1 sync/iter ---------
// C = alpha * A[M,K] @ B[N,K]^T (+ Res in mode 0).  A,B half, k-pair-permuted.
// EMODE: 0 = fp32 plain (+res), 1 = half k-permuted, 2 = half plain.
#define HSTR 12
#define HTSZ (128 * HSTR)

template <int EMODE>
__global__ void __launch_bounds__(256) hgemm_kernel(
    const __half* __restrict__ A, const __half* __restrict__ Bm,
    const float* __restrict__ Res, void* __restrict__ Cv,
    int M, int N, int K, float alpha)
{
    extern __shared__ uint2 sh2[];
    uint2* As = sh2;              // [2][HTSZ]
    uint2* Bs = sh2 + 2 * HTSZ;   // [2][HTSZ]

    const int bx = blockIdx.x, by = blockIdx.y;
    const int tid = threadIdx.x;
    const int lane = tid & 31, w = tid >> 5;
    const int wm = w & 3, wn = w >> 2;          // 4x2 warps; warp tile 32m x 64n
    const int lr = lane >> 2, lc = lane & 3;

    float acc[2][8][4];
    #pragma unroll
    for (int i = 0; i < 2; i++)
        #pragma unroll
        for (int j = 0; j < 8; j++)
            #pragma unroll
            for (int t = 0; t < 4; t++) acc[i][j][t] = 0.0f;

    const int iters = K >> 5;
    const int r_ld = tid >> 1;          // 0..127
    const int c2   = (tid & 1) * 2;     // chunk 0/2

    auto load_tile = [&](int t, int buf) {
        int k0 = t << 5;
        const __half* srcA = A + (size_t)(by * 128 + r_ld) * K + k0 + c2 * 8;
        uint32_t dA = (uint32_t)__cvta_generic_to_shared(As + buf * HTSZ + r_ld * HSTR + c2 * 2);
        cp_async16(dA,      srcA);
        cp_async16(dA + 16, srcA + 8);
        const __half* srcB = Bm + (size_t)(bx * 128 + r_ld) * K + k0 + c2 * 8;
        uint32_t dB = (uint32_t)__cvta_generic_to_shared(Bs + buf * HTSZ + r_ld * HSTR + c2 * 2);
        cp_async16(dB,      srcB);
        cp_async16(dB + 16, srcB + 8);
    };

    load_tile(0, 0);
    CP_COMMIT();

    int buf = 0;
    for (int t = 0; t < iters; t++) {
        CP_WAIT(0);
        __syncthreads();    // tile t visible; all warps done reading buf^1 (prev compute)
        if (t + 1 < iters) {
            load_tile(t + 1, buf ^ 1);
            CP_COMMIT();
        }
        const uint2* Ab = As + buf * HTSZ;
        const uint2* Bb = Bs + buf * HTSZ;
        #pragma unroll
        for (int ks = 0; ks < 2; ks++) {
            uint32_t afr[2][4];
            #pragma unroll
            for (int mt = 0; mt < 2; mt++) {
                const uint2* ap = Ab + (wm * 32 + mt * 16 + lr) * HSTR + ks * 4 + lc;
                uint2 p0 = ap[0];
                uint2 p1 = ap[8 * HSTR];
                afr[mt][0] = p0.x; afr[mt][1] = p1.x;
                afr[mt][2] = p0.y; afr[mt][3] = p1.y;
            }
            #pragma unroll
            for (int nt = 0; nt < 8; nt++) {
                const uint2* bp = Bb + (wn * 64 + nt * 8 + lr) * HSTR + ks * 4 + lc;
                uint2 bb = bp[0];
                uint32_t bfr[2] = {bb.x, bb.y};
                mma_f16(acc[0][nt], afr[0], bfr);
                mma_f16(acc[1][nt], afr[1], bfr);
            }
        }
        buf ^= 1;
    }

    // epilogue
    #pragma unroll
    for (int mt = 0; mt < 2; mt++) {
        int r0 = by * 128 + wm * 32 + mt * 16 + lr;
        #pragma unroll
        for (int nt = 0; nt < 8; nt++) {
            int c = bx * 128 + wn * 64 + nt * 8 + 2 * lc;
            float a0 = acc[mt][nt][0] * alpha, a1 = acc[mt][nt][1] * alpha;
            float a2 = acc[mt][nt][2] * alpha, a3 = acc[mt][nt][3] * alpha;
            if (EMODE == 0) {
                float* C = (float*)Cv;
                float2 lo = {a0, a1}, hi = {a2, a3};
                if (Res) {
                    float2 rlo = *(const float2*)(Res + (size_t)r0 * N + c);
                    float2 rhi = *(const float2*)(Res + (size_t)(r0 + 8) * N + c);
                    lo.x += rlo.x; lo.y += rlo.y; hi.x += rhi.x; hi.y += rhi.y;
                }
                *(float2*)(C + (size_t)r0 * N + c)       = lo;
                *(float2*)(C + (size_t)(r0 + 8) * N + c) = hi;
            } else if (EMODE == 1) {
                __half* C = (__half*)Cv;
                int hoff = (c & ~15) + 4 * lc + 2 * (nt & 1);   // permuted pair slot
                ((uint32_t*)(C + (size_t)r0 * N))[hoff >> 1]       = h2u(a0, a1);
                ((uint32_t*)(C + (size_t)(r0 + 8) * N))[hoff >> 1] = h2u(a2, a3);
            } else {
                __half* C = (__half*)Cv;
                ((uint32_t*)(C + (size_t)r0 * N))[c >> 1]       = h2u(a0, a1);
                ((uint32_t*)(C + (size_t)(r0 + 8) * N))[c >> 1] = h2u(a2, a3);
            }
        }
    }
}

// ---------------- RoPE on half k-permuted Q,K ----------------
__global__ void rope_kernel(__half* __restrict__ q, __half* __restrict__ k) {
    int idx = blockIdx.x * blockDim.x + threadIdx.x;
    if (idx >= T_ * NH_) return;
    int h  = idx & (NH_ - 1);
    int bs = idx >> 4;
    int s  = bs & (S_ - 1);
    __half* qp = q + (size_t)bs * H_ + h * HD_;
    __half* kp = k + (size_t)bs * H_ + h * HD_;
    uint4 qlo = *(uint4*)qp, qhi = *(uint4*)(qp + 8);
    uint4 klo = *(uint4*)kp, khi = *(uint4*)(kp + 8);
    float qv[16], kv[16];
    unpack16(qlo, qhi, qv);
    unpack16(klo, khi, kv);
    #pragma unroll
    for (int i = 0; i < ROT_ / 2; i++) {
        double invf = pow(10000.0, -(double)(2 * i) / (double)ROT_);
        double ang = (double)s * invf;
        float c  = (float)cos(ang);
        float sn = (float)sin(ang);
        float q0 = qv[i], q1 = qv[i + 8];
        qv[i]     = q0 * c - q1 * sn;
        qv[i + 8] = q1 * c + q0 * sn;
        float k0 = kv[i], k1 = kv[i + 8];
        kv[i]     = k0 * c - k1 * sn;
        kv[i + 8] = k1 * c + k0 * sn;
    }
    pack16(qv, qlo, qhi);
    pack16(kv, klo, khi);
    *(uint4*)qp = qlo; *(uint4*)(qp + 8) = qhi;
    *(uint4*)kp = klo; *(uint4*)(kp + 8) = khi;
}

// ---------------- fused causal attention (fp16 mma, 128-q tiles, 8 warps) ----------------
// O = (sum gelu(qk/8)*V) * sqrt(S)/sqrt(sum gelu^2). masked entries exactly 0.
// Q,K: [tok][H] half k-permuted; VT: [b,h,dim,S] half tok-permuted; O: half k-permuted.
#define VSTR 20                   // uint2 per smem row (16 uint2 data + 4 pad)
#define ATSZ (64 * VSTR)          // uint2 per 64-row tile
#define QTSZ (128 * VSTR)         // uint2 per 128-row tile

__global__ void __launch_bounds__(256, 2) attn_kernel(
    const __half* __restrict__ Q, const __half* __restrict__ K,
    const __half* __restrict__ VT, __half* __restrict__ O)
{
    extern __shared__ uint2 sm2[];
    uint2* Qs = sm2;                 // [128][VSTR]
    uint2* Ks = Qs + QTSZ;           // [2][64][VSTR]
    uint2* Vs = Ks + 2 * ATSZ;       // [2][64][VSTR]
    uint2* Ss = Vs + 2 * ATSZ;       // [128][VSTR]

    const int qt  = blockIdx.x;      // 16 q-tiles of 128
    const int bh  = blockIdx.y;
    const int b   = bh >> 4, h = bh & 15;
    const int tid = threadIdx.x;
    const int lane = tid & 31, w = tid >> 5;     // 8 warps x 16 q-rows
    const int lr = lane >> 2, lc = lane & 3;
    const size_t baseQK = (size_t)(b * S_) * H_ + h * HD_;
    const size_t baseVT = (size_t)(bh * HD_) * S_;

    // fill Q tile: 128 rows x 8 chunks of 16B
    #pragma unroll
    for (int it = 0; it < 4; it++) {
        int c = tid + it * 256;
        int r = c >> 3, off = c & 7;
        const __half* src = Q + baseQK + (size_t)(qt * 128 + r) * H_ + off * 8;
        uint32_t dst = (uint32_t)__cvta_generic_to_shared(Qs + r * VSTR + off * 2);
        cp_async16(dst, src);
    }
    // fill K/V tile j=0 into buf 0 (64 rows x 8 chunks each)
    #pragma unroll
    for (int it = 0; it < 2; it++) {
        int c = tid + it * 256;
        int r = c >> 3, off = c & 7;
        const __half* srck = K + baseQK + (size_t)r * H_ + off * 8;
        uint32_t dk = (uint32_t)__cvta_generic_to_shared(Ks + r * VSTR + off * 2);
        cp_async16(dk, srck);
        const __half* srcv = VT + baseVT + (size_t)r * S_ + off * 8;
        uint32_t dv = (uint32_t)__cvta_generic_to_shared(Vs + r * VSTR + off * 2);
        cp_async16(dv, srcv);
    }
    CP_COMMIT();

    float oacc[8][4];
    #pragma unroll
    for (int i = 0; i < 8; i++)
        #pragma unroll
        for (int j = 0; j < 4; j++) oacc[i][j] = 0.0f;
    float n2lo = 0.0f, n2hi = 0.0f;

    const int jmax = 2 * qt + 1;     // last 64-tok tile index
    int buf = 0;
    for (int j = 0; j <= jmax; j++) {
        CP_WAIT(0);
        __syncthreads();

        if (j < jmax) {
            #pragma unroll
            for (int it = 0; it < 2; it++) {
                int c = tid + it * 256;
                int r = c >> 3, off = c & 7;
                const __half* srck = K + baseQK + (size_t)((j + 1) * 64 + r) * H_ + off * 8;
                uint32_t dk = (uint32_t)__cvta_generic_to_shared(Ks + (buf ^ 1) * ATSZ + r * VSTR + off * 2);
                cp_async16(dk, srck);
                const __half* srcv = VT + baseVT + (size_t)r * S_ + (j + 1) * 64 + off * 8;
                uint32_t dv = (uint32_t)__cvta_generic_to_shared(Vs + (buf ^ 1) * ATSZ + r * VSTR + off * 2);
                cp_async16(dv, srcv);
            }
            CP_COMMIT();
        }

        const uint2* Kb = Ks + buf * ATSZ;
        const uint2* Vb = Vs + buf * ATSZ;

        // S = Q K^T (fp16 mma): per warp 16q x 64tok, 4 k16 steps
        float sacc[8][4];
        #pragma unroll
        for (int i = 0; i < 8; i++)
            #pragma unroll
            for (int jj = 0; jj < 4; jj++) sacc[i][jj] = 0.0f;
        #pragma unroll
        for (int ks = 0; ks < 4; ks++) {
            const uint2* ap = Qs + (w * 16 + lr) * VSTR + ks * 4 + lc;
            uint2 p0 = ap[0];
            uint2 p1 = ap[8 * VSTR];
            uint32_t a[4] = {p0.x, p1.x, p0.y, p1.y};
            #pragma unroll
            for (int nt = 0; nt < 8; nt++) {
                uint2 bb = Kb[(nt * 8 + lr) * VSTR + ks * 4 + lc];
                uint32_t bfr[2] = {bb.x, bb.y};
                mma_f16(sacc[nt], a, bfr);
            }
        }

        // mask + gelu + n2 + pack to Ss (half pairs, tok-permuted)
        int q0 = qt * 128 + w * 16 + lr;
        uint32_t* Ss32 = (uint32_t*)Ss;
        #pragma unroll
        for (int nt = 0; nt < 8; nt++) {
            int k0c = j * 64 + nt * 8 + 2 * lc;
            float g0 = (k0c     <= q0)     ? gelu_exact(sacc[nt][0] * 0.125f) : 0.0f;
            float g1 = (k0c + 1 <= q0)     ? gelu_exact(sacc[nt][1] * 0.125f) : 0.0f;
            float g2 = (k0c     <= q0 + 8) ? gelu_exact(sacc[nt][2] * 0.125f) : 0.0f;
            float g3 = (k0c + 1 <= q0 + 8) ? gelu_exact(sacc[nt][3] * 0.125f) : 0.0f;
            n2lo += g0 * g0 + g1 * g1;
            n2hi += g2 * g2 + g3 * g3;
            int slot = (nt >> 1) * 8 + 2 * lc + (nt & 1);       // permuted uint slot
            Ss32[(w * 16 + lr)     * (2 * VSTR) + slot] = h2u(g0, g1);
            Ss32[(w * 16 + lr + 8) * (2 * VSTR) + slot] = h2u(g2, g3);
        }
        __syncwarp();   // Ss rows are warp-private

        // O += Ss @ V (fp16 mma): 4 k16 steps over 64 toks
        #pragma unroll
        for (int ks = 0; ks < 4; ks++) {
            const uint2* ap = Ss + (w * 16 + lr) * VSTR + ks * 4 + lc;
            uint2 p0 = ap[0];
            uint2 p1 = ap[8 * VSTR];
            uint32_t a[4] = {p0.x, p1.x, p0.y, p1.y};
            #pragma unroll
            for (int nt = 0; nt < 8; nt++) {
                uint2 bb = Vb[(nt * 8 + lr) * VSTR + ks * 4 + lc];
                uint32_t bfr[2] = {bb.x, bb.y};
                mma_f16(oacc[nt], a, bfr);
            }
        }
        buf ^= 1;
    }

    n2lo += __shfl_xor_sync(0xffffffffu, n2lo, 1);
    n2lo += __shfl_xor_sync(0xffffffffu, n2lo, 2);
    n2hi += __shfl_xor_sync(0xffffffffu, n2hi, 1);
    n2hi += __shfl_xor_sync(0xffffffffu, n2hi, 2);

    const float sqS = 45.25483399593904f;
    float sclo = sqS * rsqrtf(n2lo);
    float schi = sqS * rsqrtf(n2hi);

    // store half, k-pair-permuted (feeds proj GEMM as A)
    int r0 = qt * 128 + w * 16 + lr;
    #pragma unroll
    for (int nt = 0; nt < 8; nt++) {
        int c = nt * 8 + 2 * lc;                     // even dim index within head
        int pp = (c & ~15) | (2 * hperm((c & 15) >> 1));
        __half* o0 = O + baseQK + (size_t)r0 * H_;
        __half* o1 = O + baseQK + (size_t)(r0 + 8) * H_;
        ((uint32_t*)o0)[pp >> 1] = h2u(oacc[nt][0] * sclo, oacc[nt][1] * sclo);
        ((uint32_t*)o1)[pp >> 1] = h2u(oacc[nt][2] * schi, oacc[nt][3] * schi);
    }
}

// ---------------- launch ----------------
extern "C" void kernel_launch(void* const* d_in, const int* in_sizes, int n_in,
                              void* d_out, int out_size) {
    const float* x        = (const float*)d_in[0];
    const float* ln1_w    = (const float*)d_in[1];
    const float* ln1_b    = (const float*)d_in[2];
    const float* ln2_w    = (const float*)d_in[3];
    const float* ln2_b    = (const float*)d_in[4];
    const float* q_key    = (const float*)d_in[5];
    const float* q_val    = (const float*)d_in[6];
    const float* k_key    = (const float*)d_in[7];
    const float* k_val    = (const float*)d_in[8];
    const float* v_key    = (const float*)d_in[9];
    const float* v_val    = (const float*)d_in[10];
    const float* proj_key = (const float*)d_in[11];
    const float* proj_val = (const float*)d_in[12];
    const float* ffn_key  = (const float*)d_in[13];
    const float* ffn_val  = (const float*)d_in[14];
    float* out = (float*)d_out;

    float *p_big, *p_x1;
    __half *p_xnh, *p_bigh, *p_oh, *p_qh, *p_kh, *p_vh, *p_vth;
    __half *p_qkh, *p_kkh, *p_vkh, *p_pkh, *p_fkh;
    __half *p_qvh, *p_kvh, *p_vvh, *p_pvh, *p_fvh;
    cudaGetSymbolAddress((void**)&p_big,  d_big);
    cudaGetSymbolAddress((void**)&p_x1,   d_x1);
    cudaGetSymbolAddress((void**)&p_xnh,  d_xnh);
    cudaGetSymbolAddress((void**)&p_bigh, d_bigh);
    cudaGetSymbolAddress((void**)&p_oh,   d_oh);
    cudaGetSymbolAddress((void**)&p_qh,   d_qh);
    cudaGetSymbolAddress((void**)&p_kh,   d_kh);
    cudaGetSymbolAddress((void**)&p_vh,   d_vh);
    cudaGetSymbolAddress((void**)&p_vth,  d_vth);
    cudaGetSymbolAddress((void**)&p_qkh,  d_qkh);
    cudaGetSymbolAddress((void**)&p_kkh,  d_kkh);
    cudaGetSymbolAddress((void**)&p_vkh,  d_vkh);
    cudaGetSymbolAddress((void**)&p_pkh,  d_pkh);
    cudaGetSymbolAddress((void**)&p_fkh,  d_fkh);
    cudaGetSymbolAddress((void**)&p_qvh,  d_qvh);
    cudaGetSymbolAddress((void**)&p_kvh,  d_kvh);
    cudaGetSymbolAddress((void**)&p_vvh,  d_vvh);
    cudaGetSymbolAddress((void**)&p_pvh,  d_pvh);
    cudaGetSymbolAddress((void**)&p_fvh,  d_fvh);

    const float sqrtH = 32.0f;
    dim3 g_small(H_ / 128, T_ / 128);       // (8, 32)
    dim3 g_ffn1(FFN_ / 128, T_ / 128);      // (32, 32)
    dim3 tthr(32, 8);
    dim3 tgrd(H_ / 32, H_ / 32);
    dim3 tgrd_f(H_ / 32, FFN_ / 32);

    const int smem_g = 4 * HTSZ * 8;        // 49152 bytes
    cudaFuncSetAttribute(hgemm_kernel<0>, cudaFuncAttributeMaxDynamicSharedMemorySize, smem_g);
    cudaFuncSetAttribute(hgemm_kernel<1>, cudaFuncAttributeMaxDynamicSharedMemorySize, smem_g);
    cudaFuncSetAttribute(hgemm_kernel<2>, cudaFuncAttributeMaxDynamicSharedMemorySize, smem_g);

    // preprocess weights -> half permuted
    const int n16_hh = H_ * H_ / 16, n16_fh = FFN_ * H_ / 16;
    round_perm_kernel<<<(n16_hh + 255) / 256, 256>>>(q_key,    p_qkh, n16_hh);
    round_perm_kernel<<<(n16_hh + 255) / 256, 256>>>(k_key,    p_kkh, n16_hh);
    round_perm_kernel<<<(n16_hh + 255) / 256, 256>>>(v_key,    p_vkh, n16_hh);
    round_perm_kernel<<<(n16_hh + 255) / 256, 256>>>(proj_key, p_pkh, n16_hh);
    round_perm_kernel<<<(n16_fh + 255) / 256, 256>>>(ffn_key,  p_fkh, n16_fh);
    transpose_kernel<<<tgrd,   tthr>>>(q_val,    p_qvh, H_,   H_);
    transpose_kernel<<<tgrd,   tthr>>>(k_val,    p_kvh, H_,   H_);
    transpose_kernel<<<tgrd,   tthr>>>(v_val,    p_vvh, H_,   H_);
    transpose_kernel<<<tgrd,   tthr>>>(proj_val, p_pvh, H_,   H_);
    transpose_kernel<<<tgrd_f, tthr>>>(ffn_val,  p_fvh, FFN_, H_);

    ln_kernel<<<T_, 64>>>(x, ln1_w, ln1_b, p_xnh);

    // q / k / v pattention (Q,K emitted half-perm; V half-plain)
    hgemm_kernel<0><<<g_small, 256, smem_g>>>(p_xnh, p_qkh, nullptr, p_big, T_, H_, H_, sqrtH);
    rownorm_kernel<64><<<T_, 64>>>(p_big, p_bigh, H_);
    hgemm_kernel<1><<<g_small, 256, smem_g>>>(p_bigh, p_qvh, nullptr, p_qh, T_, H_, H_, 1.0f);

    hgemm_kernel<0><<<g_small, 256, smem_g>>>(p_xnh, p_kkh, nullptr, p_big, T_, H_, H_, sqrtH);
    rownorm_kernel<64><<<T_, 64>>>(p_big, p_bigh, H_);
    hgemm_kernel<1><<<g_small, 256, smem_g>>>(p_bigh, p_kvh, nullptr, p_kh, T_, H_, H_, 1.0f);

    hgemm_kernel<0><<<g_small, 256, smem_g>>>(p_xnh, p_vkh, nullptr, p_big, T_, H_, H_, sqrtH);
    rownorm_kernel<64><<<T_, 64>>>(p_big, p_bigh, H_);
    hgemm_kernel<2><<<g_small, 256, smem_g>>>(p_bigh, p_vvh, nullptr, p_vh, T_, H_, H_, 1.0f);

    rope_kernel<<<(T_ * NH_) / 256, 256>>>(p_qh, p_kh);

    {
        dim3 vtg(S_ / 32, HD_ / 32, B_ * NH_);
        vt_kernel<<<vtg, tthr>>>(p_vh, p_vth);
    }

    {
        int smem = (2 * QTSZ + 4 * ATSZ) * 8;    // 81920 bytes
        cudaFuncSetAttribute(attn_kernel, cudaFuncAttributeMaxDynamicSharedMemorySize, smem);
        dim3 grid(S_ / 128, B_ * NH_);           // (16, 32)
        attn_kernel<<<grid, 256, smem>>>(p_qh, p_kh, p_vth, p_oh);
    }

    // proj pattention + fused residual
    hgemm_kernel<0><<<g_small, 256, smem_g>>>(p_oh, p_pkh, nullptr, p_big, T_, H_, H_, sqrtH);
    rownorm_kernel<64><<<T_, 64>>>(p_big, p_bigh, H_);
    hgemm_kernel<0><<<g_small, 256, smem_g>>>(p_bigh, p_pvh, x, p_x1, T_, H_, H_, 1.0f);

    // ffn pattention + fused residual
    ln_kernel<<<T_, 64>>>(p_x1, ln2_w, ln2_b, p_xnh);
    hgemm_kernel<0><<<g_ffn1, 256, smem_g>>>(p_xnh, p_fkh, nullptr, p_big, T_, FFN_, H_, sqrtH);
    rownorm_kernel<256><<<T_, 256>>>(p_big, p_bigh, FFN_);
    hgemm_kernel<0><<<g_small, 256, smem_g>>>(p_bigh, p_fvh, p_x1, out, T_, H_, FFN_, 1.0f);
}